// round 5
// baseline (speedup 1.0000x reference)
#include <cuda_runtime.h>
#include <math.h>

#define NN  50000
#define EE  800000
#define FIN 64
#define HH  200
#define GG  256

// ------------------------- scratch (device globals; no allocation) ---------
__device__ __align__(256) float g_T[2][(size_t)NN * 600];   // ping-pong [N][3F]
__device__ int   g_src[EE], g_dstv[EE], g_col[EE];
__device__ float g_w[EE], g_ew[EE];
__device__ int   g_deg[NN], g_indeg[NN], g_cursor[NN], g_batch[NN];
__device__ float g_dis[NN], g_diag[NN];
__device__ int   g_rowptr[NN + 1];
__device__ int   g_cnt[GG], g_gstart[GG + 1];
__device__ float g_pool[GG * 400];
__device__ int   g_is64;

// ------------------------- dtype detection + conversion --------------------
__global__ void k_detect(const void* ei) {
    const unsigned* u = (const unsigned*)ei;
    int z = 0;
    for (int i = 0; i < 32; i++)
        if (u[2 * i + 1] == 0u) z++;
    g_is64 = (z >= 16) ? 1 : 0;   // int64 little-endian: high words all zero
}

__global__ void k_cvt_edges(const void* ei) {
    int e = blockIdx.x * blockDim.x + threadIdx.x;
    if (e >= EE) return;
    if (g_is64) {
        const long long* p = (const long long*)ei;
        g_src[e]  = (int)p[e];
        g_dstv[e] = (int)p[EE + e];
    } else {
        const int* p = (const int*)ei;
        g_src[e]  = p[e];
        g_dstv[e] = p[EE + e];
    }
}

__global__ void k_cvt_batch(const void* b) {
    int n = blockIdx.x * blockDim.x + threadIdx.x;
    if (n >= NN) return;
    g_batch[n] = g_is64 ? (int)((const long long*)b)[n] : ((const int*)b)[n];
}

// ------------------------- graph preprocessing ------------------------------
__global__ void k_zero() {
    int i = blockIdx.x * blockDim.x + threadIdx.x;
    if (i < NN) { g_deg[i] = 0; g_indeg[i] = 0; g_cursor[i] = 0; }
    if (i < GG) g_cnt[i] = 0;
}

__global__ void k_deg() {
    int e = blockIdx.x * blockDim.x + threadIdx.x;
    if (e >= EE) return;
    atomicAdd(&g_deg[g_src[e]], 1);     // out-degree (by src) for normalization
    atomicAdd(&g_indeg[g_dstv[e]], 1);  // in-degree (by dst) for CSR
}

__global__ void k_node(const float* __restrict__ lmax) {
    int n = blockIdx.x * blockDim.x + threadIdx.x;
    if (n >= NN) return;
    int d = g_deg[n];
    g_dis[n]  = (d > 0) ? (1.0f / sqrtf((float)d)) : 0.0f;
    g_diag[n] = 2.0f / lmax[g_batch[n]] - 1.0f;
}

__global__ void k_ew(const float* __restrict__ lmax) {
    int e = blockIdx.x * blockDim.x + threadIdx.x;
    if (e >= EE) return;
    int s = g_src[e], d = g_dstv[e];
    g_w[e] = -g_dis[s] * g_dis[d] * (2.0f / lmax[g_batch[s]]);
}

// exclusive scan of in-degree -> rowptr (single block, chunked Hillis-Steele)
__global__ void k_scan_rowptr() {
    __shared__ int s[1024];
    __shared__ int carry;
    int tid = threadIdx.x;
    if (tid == 0) carry = 0;
    __syncthreads();
    for (int base = 0; base < NN; base += 1024) {
        int i = base + tid;
        int v = (i < NN) ? g_indeg[i] : 0;
        int xv = v;
        for (int off = 1; off < 1024; off <<= 1) {
            s[tid] = xv; __syncthreads();
            if (tid >= off) xv += s[tid - off];
            __syncthreads();
        }
        int c = carry;
        if (i < NN) g_rowptr[i] = c + xv - v;
        __syncthreads();
        if (tid == 1023) carry = c + xv;
        __syncthreads();
    }
    if (tid == 0) g_rowptr[NN] = EE;
}

__global__ void k_fill() {
    int e = blockIdx.x * blockDim.x + threadIdx.x;
    if (e >= EE) return;
    int d = g_dstv[e];
    int pos = g_rowptr[d] + atomicAdd(&g_cursor[d], 1);
    g_col[pos] = g_src[e];
    g_ew[pos]  = g_w[e];
}

__global__ void k_copyx(const float* __restrict__ x) {
    int i = blockIdx.x * blockDim.x + threadIdx.x;
    if (i >= NN * FIN) return;
    int n = i >> 6, f = i & 63;
    g_T[0][(size_t)n * 192 + f] = x[i];
}

// ------------------------- sparse propagation (gather-based, warp/node) -----
// out[n] = alpha * ( sum_{e in row n} w_e * hs[col_e] + diag[n]*hs[n] ) + beta*slice0[n]
template <int F, int LD>
__global__ void k_prop(int sel, int srcS, int dstS, float alpha, float beta, int useSub) {
    int w = (blockIdx.x * blockDim.x + threadIdx.x) >> 5;
    if (w >= NN) return;
    int lane = threadIdx.x & 31;
    float* base = g_T[sel];
    const float* hs  = base + srcS * F;
    float*       out = base + dstS * F;
    const float* sub = base;              // slice 0
    constexpr int NJ = (F + 31) / 32;
    float acc[NJ];
#pragma unroll
    for (int j = 0; j < NJ; j++) acc[j] = 0.0f;

    int e = g_rowptr[w], eend = g_rowptr[w + 1];
    for (; e < eend; e++) {
        int   c  = __ldg(&g_col[e]);
        float we = __ldg(&g_ew[e]);
        const float* row = hs + (size_t)c * LD;
#pragma unroll
        for (int j = 0; j < NJ; j++) {
            int f = lane + 32 * j;
            if (f < F) acc[j] += we * row[f];
        }
    }
    float dg = g_diag[w];
    const float* hrow = hs  + (size_t)w * LD;
    float*       orow = out + (size_t)w * LD;
    const float* srow = sub + (size_t)w * LD;
#pragma unroll
    for (int j = 0; j < NJ; j++) {
        int f = lane + 32 * j;
        if (f < F) {
            float v = alpha * (acc[j] + dg * hrow[f]);
            if (useSub) v += beta * srow[f];
            orow[f] = v;
        }
    }
}

// ------------------------- SGEMM: C = relu(A[N,Kd] @ W[Kd,200] + b) ---------
// A = g_T[selA] (row stride Kd); C = g_T[selC] slice0 (row stride 600)
__global__ __launch_bounds__(256, 2) void k_gemm(int selA, int Kd,
                                                 const float* __restrict__ Wm,
                                                 const float* __restrict__ bias,
                                                 int selC) {
    const int BM = 128, BNt = 128, BK = 8;
    const int M = NN, Nn = HH, ldw = HH, ldc = 600;
    const float* A = g_T[selA];
    float*       C = g_T[selC];
    __shared__ float As[BK][BM];
    __shared__ float Bs[BK][BNt];

    int tid = threadIdx.x;
    int m0 = blockIdx.y * BM;
    int n0 = blockIdx.x * BNt;
    int tx = tid & 15, ty = tid >> 4;

    int arow = tid >> 1;            // 0..127
    int ak   = (tid & 1) * 4;       // 0 or 4
    int bk   = tid >> 5;            // 0..7
    int bcol = (tid & 31) * 4;      // 0..124

    float acc[8][8];
#pragma unroll
    for (int i = 0; i < 8; i++)
#pragma unroll
        for (int j = 0; j < 8; j++) acc[i][j] = 0.0f;

    for (int k0 = 0; k0 < Kd; k0 += BK) {
        {   // load A tile (128 x 8), transposed into smem
            int gm = m0 + arow;
            float4 v = make_float4(0.f, 0.f, 0.f, 0.f);
            if (gm < M) v = *(const float4*)(A + (size_t)gm * Kd + k0 + ak);
            As[ak + 0][arow] = v.x;
            As[ak + 1][arow] = v.y;
            As[ak + 2][arow] = v.z;
            As[ak + 3][arow] = v.w;
        }
        {   // load W tile (8 x 128)
            int gn = n0 + bcol;
            float4 v = make_float4(0.f, 0.f, 0.f, 0.f);
            if (gn < Nn) v = *(const float4*)(Wm + (size_t)(k0 + bk) * ldw + gn);
            *(float4*)&Bs[bk][bcol] = v;
        }
        __syncthreads();
#pragma unroll
        for (int k = 0; k < BK; k++) {
            float a[8], b[8];
            *(float4*)&a[0] = *(const float4*)&As[k][ty * 8];
            *(float4*)&a[4] = *(const float4*)&As[k][ty * 8 + 4];
            *(float4*)&b[0] = *(const float4*)&Bs[k][tx * 8];
            *(float4*)&b[4] = *(const float4*)&Bs[k][tx * 8 + 4];
#pragma unroll
            for (int i = 0; i < 8; i++)
#pragma unroll
                for (int j = 0; j < 8; j++) acc[i][j] += a[i] * b[j];
        }
        __syncthreads();
    }

#pragma unroll
    for (int i = 0; i < 8; i++) {
        int gm = m0 + ty * 8 + i;
        if (gm >= M) continue;
#pragma unroll
        for (int j = 0; j < 8; j++) {
            int gn = n0 + tx * 8 + j;
            if (gn < Nn) {
                float v = acc[i][j] + bias[gn];
                v = fmaxf(v, 0.0f);    // all 4 layers use relu
                C[(size_t)gm * ldc + gn] = v;
            }
        }
    }
}

// ------------------------- pooling + fc + log_softmax -----------------------
__global__ void k_cnt() {
    int n = blockIdx.x * blockDim.x + threadIdx.x;
    if (n >= NN) return;
    atomicAdd(&g_cnt[g_batch[n]], 1);
}

__global__ void k_scan_g() {
    __shared__ int s[GG];
    int tid = threadIdx.x;
    int v = g_cnt[tid];
    int xv = v;
    for (int off = 1; off < GG; off <<= 1) {
        s[tid] = xv; __syncthreads();
        if (tid >= off) xv += s[tid - off];
        __syncthreads();
    }
    g_gstart[tid] = xv - v;
    if (tid == GG - 1) g_gstart[GG] = xv;
}

__global__ void k_pool() {   // one block per graph, final h lives in g_T[0], ld=600
    int g = blockIdx.x, f = threadIdx.x;
    if (f >= HH) return;
    int s = g_gstart[g], e = g_gstart[g + 1];
    float sum = 0.0f, mx = -3.4e38f;
    const float* base = g_T[0];
    for (int n = s; n < e; n++) {
        float v = base[(size_t)n * 600 + f];
        sum += v;
        mx = fmaxf(mx, v);
    }
    float c = (float)(e - s);
    g_pool[g * 400 + f]      = sum / fmaxf(c, 1.0f);
    g_pool[g * 400 + HH + f] = mx;
}

__global__ void k_fc(const float* __restrict__ fw, const float* __restrict__ fb,
                     float* __restrict__ out) {
    int g = blockIdx.x * blockDim.x + threadIdx.x;
    if (g >= GG) return;
    float z0 = fb[0], z1 = fb[1];
    const float* p = &g_pool[g * 400];
    for (int j = 0; j < 400; j++) {
        float v = p[j];
        z0 += v * fw[2 * j];
        z1 += v * fw[2 * j + 1];
    }
    float m = fmaxf(z0, z1);
    float l = m + logf(expf(z0 - m) + expf(z1 - m));
    out[2 * g]     = z0 - l;
    out[2 * g + 1] = z1 - l;
}

// ------------------------- launch ------------------------------------------
extern "C" void kernel_launch(void* const* d_in, const int* in_sizes, int n_in,
                              void* d_out, int out_size) {
    const float* x     = (const float*)d_in[0];
    const void*  ei    = d_in[1];
    const void*  batch = d_in[2];
    const float* lmax  = (const float*)d_in[3];
    const float* W1 = (const float*)d_in[4];  const float* b1 = (const float*)d_in[5];
    const float* W2 = (const float*)d_in[6];  const float* b2 = (const float*)d_in[7];
    const float* W3 = (const float*)d_in[8];  const float* b3 = (const float*)d_in[9];
    const float* W4 = (const float*)d_in[10]; const float* b4 = (const float*)d_in[11];
    const float* fw = (const float*)d_in[12]; const float* fb = (const float*)d_in[13];
    float* out = (float*)d_out;

    const int TB = 256;
    int nbN = (NN + TB - 1) / TB;
    int nbE = (EE + TB - 1) / TB;

    k_detect<<<1, 1>>>(ei);
    k_zero<<<nbN, TB>>>();
    k_cvt_edges<<<nbE, TB>>>(ei);
    k_cvt_batch<<<nbN, TB>>>(batch);
    k_deg<<<nbE, TB>>>();
    k_node<<<nbN, TB>>>(lmax);
    k_ew<<<nbE, TB>>>(lmax);
    k_scan_rowptr<<<1, 1024>>>();
    k_fill<<<nbE, TB>>>();
    k_copyx<<<(NN * FIN + TB - 1) / TB, TB>>>(x);

    int propBlocks = (NN * 32 + TB - 1) / TB;   // one warp per node
    dim3 gg(2, (NN + 127) / 128);

    // layer 1: input in g_T[0] (ld=192), output -> g_T[1] slice0 (ld=600)
    k_prop<64, 192><<<propBlocks, TB>>>(0, 0, 1, 1.0f, 0.0f, 0);
    k_prop<64, 192><<<propBlocks, TB>>>(0, 1, 2, 2.0f, -1.0f, 1);
    k_gemm<<<gg, TB>>>(0, 192, W1, b1, 1);

    // layer 2: g_T[1] -> g_T[0]
    k_prop<200, 600><<<propBlocks, TB>>>(1, 0, 1, 1.0f, 0.0f, 0);
    k_prop<200, 600><<<propBlocks, TB>>>(1, 1, 2, 2.0f, -1.0f, 1);
    k_gemm<<<gg, TB>>>(1, 600, W2, b2, 0);

    // layer 3: g_T[0] -> g_T[1]
    k_prop<200, 600><<<propBlocks, TB>>>(0, 0, 1, 1.0f, 0.0f, 0);
    k_prop<200, 600><<<propBlocks, TB>>>(0, 1, 2, 2.0f, -1.0f, 1);
    k_gemm<<<gg, TB>>>(0, 600, W3, b3, 1);

    // layer 4: g_T[1] -> g_T[0]
    k_prop<200, 600><<<propBlocks, TB>>>(1, 0, 1, 1.0f, 0.0f, 0);
    k_prop<200, 600><<<propBlocks, TB>>>(1, 1, 2, 2.0f, -1.0f, 1);
    k_gemm<<<gg, TB>>>(1, 600, W4, b4, 0);

    // pooling over sorted batch, then fc + log_softmax
    k_cnt<<<nbN, TB>>>();
    k_scan_g<<<1, GG>>>();
    k_pool<<<GG, TB>>>();
    k_fc<<<1, GG>>>(fw, fb, out);
}

// round 7
// speedup vs baseline: 1.1057x; 1.1057x over previous
#include <cuda_runtime.h>
#include <cuda_bf16.h>
#include <math.h>
#include <stdint.h>

#define NN  50000
#define EE  800000
#define FIN 64
#define HH  200
#define GG  256

#define LDK_BIG 640   // 3*200 padded to /64
#define LDK_S   192   // 3*64

// ------------------------- scratch (device globals; no allocation) ---------
__device__ __align__(256) float g_T[2][(size_t)NN * 600];   // ping-pong [N][3F]
__device__ __align__(256) __nv_bfloat16 g_Ah[(size_t)NN * LDK_BIG];
__device__ __align__(256) __nv_bfloat16 g_Al[(size_t)NN * LDK_BIG];
__device__ __align__(256) __nv_bfloat16 g_Bh[256 * LDK_BIG];
__device__ __align__(256) __nv_bfloat16 g_Bl[256 * LDK_BIG];
__device__ int   g_src[EE], g_dstv[EE], g_col[EE];
__device__ float g_w[EE], g_ew[EE];
__device__ int   g_deg[NN], g_indeg[NN], g_cursor[NN], g_batch[NN];
__device__ float g_dis[NN], g_diag[NN];
__device__ int   g_rowptr[NN + 1];
__device__ int   g_cnt[GG], g_gstart[GG + 1];
__device__ float g_pool[GG * 400];
__device__ int   g_is64;

__device__ __forceinline__ uint32_t smem_to_u32(const void* p) {
    uint32_t a;
    asm("{ .reg .u64 t; cvta.to.shared.u64 t, %1; cvt.u32.u64 %0, t; }" : "=r"(a) : "l"(p));
    return a;
}

// ------------------------- dtype detection + conversion --------------------
__global__ void k_detect(const void* ei) {
    const unsigned* u = (const unsigned*)ei;
    int z = 0;
    for (int i = 0; i < 32; i++)
        if (u[2 * i + 1] == 0u) z++;
    g_is64 = (z >= 16) ? 1 : 0;
}

__global__ void k_cvt_edges(const void* ei) {
    int e = blockIdx.x * blockDim.x + threadIdx.x;
    if (e >= EE) return;
    if (g_is64) {
        const long long* p = (const long long*)ei;
        g_src[e]  = (int)p[e];
        g_dstv[e] = (int)p[EE + e];
    } else {
        const int* p = (const int*)ei;
        g_src[e]  = p[e];
        g_dstv[e] = p[EE + e];
    }
}

__global__ void k_cvt_batch(const void* b) {
    int n = blockIdx.x * blockDim.x + threadIdx.x;
    if (n >= NN) return;
    g_batch[n] = g_is64 ? (int)((const long long*)b)[n] : ((const int*)b)[n];
}

// ------------------------- graph preprocessing ------------------------------
__global__ void k_zero() {
    int i = blockIdx.x * blockDim.x + threadIdx.x;
    if (i < NN) { g_deg[i] = 0; g_indeg[i] = 0; g_cursor[i] = 0; }
    if (i < GG) g_cnt[i] = 0;
}

__global__ void k_deg() {
    int e = blockIdx.x * blockDim.x + threadIdx.x;
    if (e >= EE) return;
    atomicAdd(&g_deg[g_src[e]], 1);
    atomicAdd(&g_indeg[g_dstv[e]], 1);
}

__global__ void k_node(const float* __restrict__ lmax) {
    int n = blockIdx.x * blockDim.x + threadIdx.x;
    if (n >= NN) return;
    int d = g_deg[n];
    g_dis[n]  = (d > 0) ? (1.0f / sqrtf((float)d)) : 0.0f;
    g_diag[n] = 2.0f / lmax[g_batch[n]] - 1.0f;
}

__global__ void k_ew(const float* __restrict__ lmax) {
    int e = blockIdx.x * blockDim.x + threadIdx.x;
    if (e >= EE) return;
    int s = g_src[e], d = g_dstv[e];
    g_w[e] = -g_dis[s] * g_dis[d] * (2.0f / lmax[g_batch[s]]);
}

__global__ void k_scan_rowptr() {
    __shared__ int s[1024];
    __shared__ int carry;
    int tid = threadIdx.x;
    if (tid == 0) carry = 0;
    __syncthreads();
    for (int base = 0; base < NN; base += 1024) {
        int i = base + tid;
        int v = (i < NN) ? g_indeg[i] : 0;
        int xv = v;
        for (int off = 1; off < 1024; off <<= 1) {
            s[tid] = xv; __syncthreads();
            if (tid >= off) xv += s[tid - off];
            __syncthreads();
        }
        int c = carry;
        if (i < NN) g_rowptr[i] = c + xv - v;
        __syncthreads();
        if (tid == 1023) carry = c + xv;
        __syncthreads();
    }
    if (tid == 0) g_rowptr[NN] = EE;
}

__global__ void k_fill() {
    int e = blockIdx.x * blockDim.x + threadIdx.x;
    if (e >= EE) return;
    int d = g_dstv[e];
    int pos = g_rowptr[d] + atomicAdd(&g_cursor[d], 1);
    g_col[pos] = g_src[e];
    g_ew[pos]  = g_w[e];
}

__global__ void k_copyx(const float* __restrict__ x) {
    int i = blockIdx.x * blockDim.x + threadIdx.x;
    if (i >= NN * FIN) return;
    int n = i >> 6, f = i & 63;
    g_T[0][(size_t)n * 192 + f] = x[i];
}

// ------------------------- sparse propagation (gather, warp/node) -----------
template <int F, int LD>
__global__ void k_prop(int sel, int srcS, int dstS, float alpha, float beta, int useSub) {
    int w = (blockIdx.x * blockDim.x + threadIdx.x) >> 5;
    if (w >= NN) return;
    int lane = threadIdx.x & 31;
    float* base = g_T[sel];
    const float* hs  = base + srcS * F;
    float*       out = base + dstS * F;
    const float* sub = base;
    constexpr int NJ = (F + 31) / 32;
    float acc[NJ];
#pragma unroll
    for (int j = 0; j < NJ; j++) acc[j] = 0.0f;

    int e = g_rowptr[w], eend = g_rowptr[w + 1];
    for (; e < eend; e++) {
        int   c  = __ldg(&g_col[e]);
        float we = __ldg(&g_ew[e]);
        const float* row = hs + (size_t)c * LD;
#pragma unroll
        for (int j = 0; j < NJ; j++) {
            int f = lane + 32 * j;
            if (f < F) acc[j] += we * row[f];
        }
    }
    float dg = g_diag[w];
    const float* hrow = hs  + (size_t)w * LD;
    float*       orow = out + (size_t)w * LD;
    const float* srow = sub + (size_t)w * LD;
#pragma unroll
    for (int j = 0; j < NJ; j++) {
        int f = lane + 32 * j;
        if (f < F) {
            float v = alpha * (acc[j] + dg * hrow[f]);
            if (useSub) v += beta * srow[f];
            orow[f] = v;
        }
    }
}

// ------------------------- bf16-split conversions ---------------------------
__global__ void k_cvtA(int sel, int F3, int LDK) {
    int k = blockIdx.x * 64 + threadIdx.x;
    int n = blockIdx.y;
    if (k >= LDK) return;
    float a = (k < F3) ? g_T[sel][(size_t)n * F3 + k] : 0.0f;
    __nv_bfloat16 h = __float2bfloat16(a);
    __nv_bfloat16 l = __float2bfloat16(a - __bfloat162float(h));
    size_t o = (size_t)n * LDK + k;
    g_Ah[o] = h;
    g_Al[o] = l;
}

__global__ void k_cvtB(const float* __restrict__ W, int Kd, int LDK) {
    int k = blockIdx.x * 64 + threadIdx.x;
    int n = blockIdx.y;
    if (k >= LDK) return;
    float v = (n < HH && k < Kd) ? W[(size_t)k * HH + n] : 0.0f;
    __nv_bfloat16 h = __float2bfloat16(v);
    __nv_bfloat16 l = __float2bfloat16(v - __bfloat162float(h));
    size_t o = (size_t)n * LDK + k;
    g_Bh[o] = h;
    g_Bl[o] = l;
}

// ------------------------- HMMA GEMM (mma.sync bf16, fp32 acc) -------------
// C[gm][col] = relu(sum_k A[gm][k]*B[col][k] + bias[col]), col < 200
// CTA: BM=128 rows, BN=224 cols, K chunks of 64; 8 warps = 2(m) x 4(n).
// smem: padded stride 72 bf16 (144 B) rows -> ldmatrix conflict-free.
#define SA_B   144                    // bytes per smem row (72 bf16)
#define SM_AH  0
#define SM_AL  (128 * SA_B)           // 18432
#define SM_BH  (2 * 128 * SA_B)      // 36864
#define SM_BL  (SM_BH + 224 * SA_B)  // 69120
#define SM_TOT (SM_BL + 224 * SA_B)  // 101376

__device__ __forceinline__ void ldsm_x4(uint32_t addr, uint32_t& r0, uint32_t& r1,
                                        uint32_t& r2, uint32_t& r3) {
    asm volatile("ldmatrix.sync.aligned.m8n8.x4.shared.b16 {%0,%1,%2,%3}, [%4];"
                 : "=r"(r0), "=r"(r1), "=r"(r2), "=r"(r3) : "r"(addr));
}
__device__ __forceinline__ void ldsm_x2(uint32_t addr, uint32_t& r0, uint32_t& r1) {
    asm volatile("ldmatrix.sync.aligned.m8n8.x2.shared.b16 {%0,%1}, [%2];"
                 : "=r"(r0), "=r"(r1) : "r"(addr));
}
__device__ __forceinline__ void mma16816(float* c, const uint32_t* a, const uint32_t* b) {
    asm volatile(
        "mma.sync.aligned.m16n8k16.row.col.f32.bf16.bf16.f32 "
        "{%0,%1,%2,%3}, {%4,%5,%6,%7}, {%8,%9}, {%0,%1,%2,%3};"
        : "+f"(c[0]), "+f"(c[1]), "+f"(c[2]), "+f"(c[3])
        : "r"(a[0]), "r"(a[1]), "r"(a[2]), "r"(a[3]), "r"(b[0]), "r"(b[1]));
}

__global__ __launch_bounds__(256, 1) void k_gemm_mma(int LDK, int nch,
                                                     const float* __restrict__ bias,
                                                     int selC) {
    extern __shared__ char sm[];
    uint32_t sb = smem_to_u32(sm);
    int tid = threadIdx.x, lane = tid & 31, wid = tid >> 5;
    int m0 = blockIdx.x * 128;
    int warpM = wid >> 2, warpN = wid & 3;      // 2 x 4
    int mrow0 = warpM * 64;                     // 4 m16 tiles
    int ncol0 = warpN * 56;                     // 7 n8 tiles
    const int ldk8 = LDK >> 3;

    const uint4* GAh = (const uint4*)g_Ah;
    const uint4* GAl = (const uint4*)g_Al;
    const uint4* GBh = (const uint4*)g_Bh;
    const uint4* GBl = (const uint4*)g_Bl;

    float acc[4][7][4];
#pragma unroll
    for (int i = 0; i < 4; i++)
#pragma unroll
        for (int j = 0; j < 7; j++)
#pragma unroll
            for (int q = 0; q < 4; q++) acc[i][j][q] = 0.0f;

    // lane-invariant ldmatrix address components
    int rr = lane & 7;
    int aRow = rr + 8 * ((lane >> 3) & 1);      // row-in-tile for A frag
    int aK   = 8 * (lane >> 4);                 // k-half for A frag (elems)
    int bg   = lane >> 3;                       // 0..3 groups for B x4
    int bRow = rr + 8 * (bg >> 1);
    int bK   = 8 * (bg & 1);
    int bg2  = bg & 1;                          // x2 variant (all lanes valid)

    for (int c = 0; c < nch; c++) {
        int k8 = c * 8;   // uint4 offset of chunk within row
        uint4 z = make_uint4(0u, 0u, 0u, 0u);
#pragma unroll
        for (int i = 0; i < 4; i++) {           // A: 1024 uint4 per split
            int idx = i * 256 + tid;
            int row = idx >> 3, cc = idx & 7;
            int gm = m0 + row;
            uint4 vh = z, vl = z;
            if (gm < NN) {
                size_t gi = (size_t)gm * ldk8 + k8 + cc;
                vh = GAh[gi]; vl = GAl[gi];
            }
            int off = row * SA_B + cc * 16;
            *(uint4*)(sm + SM_AH + off) = vh;
            *(uint4*)(sm + SM_AL + off) = vl;
        }
#pragma unroll
        for (int i = 0; i < 7; i++) {           // B: 1792 uint4 per split
            int idx = i * 256 + tid;
            int row = idx >> 3, cc = idx & 7;   // row < 224
            size_t gi = (size_t)row * ldk8 + k8 + cc;
            uint4 vh = GBh[gi], vl = GBl[gi];
            int off = row * SA_B + cc * 16;
            *(uint4*)(sm + SM_BH + off) = vh;
            *(uint4*)(sm + SM_BL + off) = vl;
        }
        __syncthreads();

#pragma unroll
        for (int ks = 0; ks < 4; ks++) {
            int kel = ks * 16;
            uint32_t bh[7][2], bl[7][2];
#pragma unroll
            for (int p = 0; p < 3; p++) {       // tiles 2p, 2p+1
                uint32_t boff = (uint32_t)((ncol0 + p * 16 + bRow) * SA_B + (kel + bK) * 2);
                ldsm_x4(sb + SM_BH + boff, bh[2*p][0], bh[2*p][1], bh[2*p+1][0], bh[2*p+1][1]);
                ldsm_x4(sb + SM_BL + boff, bl[2*p][0], bl[2*p][1], bl[2*p+1][0], bl[2*p+1][1]);
            }
            {                                   // tile 6 via x2
                uint32_t boff = (uint32_t)((ncol0 + 48 + rr) * SA_B + (kel + 8 * bg2) * 2);
                ldsm_x2(sb + SM_BH + boff, bh[6][0], bh[6][1]);
                ldsm_x2(sb + SM_BL + boff, bl[6][0], bl[6][1]);
            }
#pragma unroll
            for (int mt = 0; mt < 4; mt++) {
                uint32_t aoff = (uint32_t)((mrow0 + mt * 16 + aRow) * SA_B + (kel + aK) * 2);
                uint32_t ah[4], al[4];
                ldsm_x4(sb + SM_AH + aoff, ah[0], ah[1], ah[2], ah[3]);
                ldsm_x4(sb + SM_AL + aoff, al[0], al[1], al[2], al[3]);
#pragma unroll
                for (int nt = 0; nt < 7; nt++) {
                    mma16816(acc[mt][nt], ah, bh[nt]);
                    mma16816(acc[mt][nt], ah, bl[nt]);
                    mma16816(acc[mt][nt], al, bh[nt]);
                }
            }
        }
        __syncthreads();
    }

    // epilogue: bias + relu, direct from registers
    float* C = g_T[selC];
    int qrow = lane >> 2, qcol = (lane & 3) * 2;
#pragma unroll
    for (int mt = 0; mt < 4; mt++) {
        int row = m0 + mrow0 + mt * 16 + qrow;
#pragma unroll
        for (int nt = 0; nt < 7; nt++) {
            int col = ncol0 + nt * 8 + qcol;
            if (col + 1 < HH + 1 && col < HH) {
                float bz0 = __ldg(&bias[col]);
                float bz1 = __ldg(&bias[col + 1]);
                if (row < NN) {
                    C[(size_t)row * 600 + col]     = fmaxf(acc[mt][nt][0] + bz0, 0.0f);
                    C[(size_t)row * 600 + col + 1] = fmaxf(acc[mt][nt][1] + bz1, 0.0f);
                }
                if (row + 8 < NN) {
                    C[(size_t)(row + 8) * 600 + col]     = fmaxf(acc[mt][nt][2] + bz0, 0.0f);
                    C[(size_t)(row + 8) * 600 + col + 1] = fmaxf(acc[mt][nt][3] + bz1, 0.0f);
                }
            }
        }
    }
}

// ------------------------- pooling + fc + log_softmax -----------------------
__global__ void k_cnt() {
    int n = blockIdx.x * blockDim.x + threadIdx.x;
    if (n >= NN) return;
    atomicAdd(&g_cnt[g_batch[n]], 1);
}

__global__ void k_scan_g() {
    __shared__ int s[GG];
    int tid = threadIdx.x;
    int v = g_cnt[tid];
    int xv = v;
    for (int off = 1; off < GG; off <<= 1) {
        s[tid] = xv; __syncthreads();
        if (tid >= off) xv += s[tid - off];
        __syncthreads();
    }
    g_gstart[tid] = xv - v;
    if (tid == GG - 1) g_gstart[GG] = xv;
}

__global__ void k_pool() {
    int g = blockIdx.x, f = threadIdx.x;
    if (f >= HH) return;
    int s = g_gstart[g], e = g_gstart[g + 1];
    float sum = 0.0f, mx = -3.4e38f;
    const float* base = g_T[0];
    for (int n = s; n < e; n++) {
        float v = base[(size_t)n * 600 + f];
        sum += v;
        mx = fmaxf(mx, v);
    }
    float c = (float)(e - s);
    g_pool[g * 400 + f]      = sum / fmaxf(c, 1.0f);
    g_pool[g * 400 + HH + f] = mx;
}

__global__ void k_fc(const float* __restrict__ fw, const float* __restrict__ fb,
                     float* __restrict__ out) {
    int g = blockIdx.x * blockDim.x + threadIdx.x;
    if (g >= GG) return;
    float z0 = fb[0], z1 = fb[1];
    const float* p = &g_pool[g * 400];
    for (int j = 0; j < 400; j++) {
        float v = p[j];
        z0 += v * fw[2 * j];
        z1 += v * fw[2 * j + 1];
    }
    float m = fmaxf(z0, z1);
    float l = m + logf(expf(z0 - m) + expf(z1 - m));
    out[2 * g]     = z0 - l;
    out[2 * g + 1] = z1 - l;
}

// ------------------------- launch ------------------------------------------
extern "C" void kernel_launch(void* const* d_in, const int* in_sizes, int n_in,
                              void* d_out, int out_size) {
    const float* x     = (const float*)d_in[0];
    const void*  ei    = d_in[1];
    const void*  batch = d_in[2];
    const float* lmax  = (const float*)d_in[3];
    const float* W1 = (const float*)d_in[4];  const float* b1 = (const float*)d_in[5];
    const float* W2 = (const float*)d_in[6];  const float* b2 = (const float*)d_in[7];
    const float* W3 = (const float*)d_in[8];  const float* b3 = (const float*)d_in[9];
    const float* W4 = (const float*)d_in[10]; const float* b4 = (const float*)d_in[11];
    const float* fw = (const float*)d_in[12]; const float* fb = (const float*)d_in[13];
    float* out = (float*)d_out;

    cudaFuncSetAttribute(k_gemm_mma, cudaFuncAttributeMaxDynamicSharedMemorySize, SM_TOT);

    const int TB = 256;
    int nbN = (NN + TB - 1) / TB;
    int nbE = (EE + TB - 1) / TB;

    k_detect<<<1, 1>>>(ei);
    k_zero<<<nbN, TB>>>();
    k_cvt_edges<<<nbE, TB>>>(ei);
    k_cvt_batch<<<nbN, TB>>>(batch);
    k_deg<<<nbE, TB>>>();
    k_node<<<nbN, TB>>>(lmax);
    k_ew<<<nbE, TB>>>(lmax);
    k_scan_rowptr<<<1, 1024>>>();
    k_fill<<<nbE, TB>>>();
    k_copyx<<<(NN * FIN + TB - 1) / TB, TB>>>(x);

    int propBlocks = (NN * 32 + TB - 1) / TB;   // one warp per node
    int gemmBlocks = (NN + 127) / 128;          // 391

    dim3 cvtS((LDK_S + 63) / 64, NN), cvtSB((LDK_S + 63) / 64, 256);
    dim3 cvtB((LDK_BIG + 63) / 64, NN), cvtBB((LDK_BIG + 63) / 64, 256);

    // layer 1: input g_T[0] (ld 192) -> g_T[1] slice0
    k_prop<64, 192><<<propBlocks, TB>>>(0, 0, 1, 1.0f, 0.0f, 0);
    k_prop<64, 192><<<propBlocks, TB>>>(0, 1, 2, 2.0f, -1.0f, 1);
    k_cvtA<<<cvtS, 64>>>(0, 192, LDK_S);
    k_cvtB<<<cvtSB, 64>>>(W1, 192, LDK_S);
    k_gemm_mma<<<gemmBlocks, 256, SM_TOT>>>(LDK_S, LDK_S / 64, b1, 1);

    // layer 2: g_T[1] -> g_T[0]
    k_prop<200, 600><<<propBlocks, TB>>>(1, 0, 1, 1.0f, 0.0f, 0);
    k_prop<200, 600><<<propBlocks, TB>>>(1, 1, 2, 2.0f, -1.0f, 1);
    k_cvtA<<<cvtB, 64>>>(1, 600, LDK_BIG);
    k_cvtB<<<cvtBB, 64>>>(W2, 600, LDK_BIG);
    k_gemm_mma<<<gemmBlocks, 256, SM_TOT>>>(LDK_BIG, LDK_BIG / 64, b2, 0);

    // layer 3: g_T[0] -> g_T[1]
    k_prop<200, 600><<<propBlocks, TB>>>(0, 0, 1, 1.0f, 0.0f, 0);
    k_prop<200, 600><<<propBlocks, TB>>>(0, 1, 2, 2.0f, -1.0f, 1);
    k_cvtA<<<cvtB, 64>>>(0, 600, LDK_BIG);
    k_cvtB<<<cvtBB, 64>>>(W3, 600, LDK_BIG);
    k_gemm_mma<<<gemmBlocks, 256, SM_TOT>>>(LDK_BIG, LDK_BIG / 64, b3, 1);

    // layer 4: g_T[1] -> g_T[0]
    k_prop<200, 600><<<propBlocks, TB>>>(1, 0, 1, 1.0f, 0.0f, 0);
    k_prop<200, 600><<<propBlocks, TB>>>(1, 1, 2, 2.0f, -1.0f, 1);
    k_cvtA<<<cvtB, 64>>>(1, 600, LDK_BIG);
    k_cvtB<<<cvtBB, 64>>>(W4, 600, LDK_BIG);
    k_gemm_mma<<<gemmBlocks, 256, SM_TOT>>>(LDK_BIG, LDK_BIG / 64, b4, 0);

    // pooling over sorted batch, then fc + log_softmax
    k_cnt<<<nbN, TB>>>();
    k_scan_g<<<1, GG>>>();
    k_pool<<<GG, TB>>>();
    k_fc<<<1, GG>>>(fw, fb, out);
}

// round 8
// speedup vs baseline: 1.6826x; 1.5217x over previous
#include <cuda_runtime.h>
#include <cuda_bf16.h>
#include <math.h>
#include <stdint.h>

#define NN  50000
#define EE  800000
#define FIN 64
#define HH  200
#define GG  256

#define LDK_BIG 640   // 3*200 padded to /64
#define LDK_S   192   // 3*64

// ------------------------- scratch (device globals; no allocation) ---------
__device__ __align__(256) float g_T[2][(size_t)NN * 600];   // ping-pong fp32 [N][3F]
// ping-pong bf16 hi/lo A operand buffers (written by copyx/prop/epilogue)
__device__ __align__(256) __nv_bfloat16 g_AH[2][(size_t)NN * LDK_BIG];
__device__ __align__(256) __nv_bfloat16 g_AL[2][(size_t)NN * LDK_BIG];
__device__ __align__(256) __nv_bfloat16 g_Bh[256 * LDK_BIG];
__device__ __align__(256) __nv_bfloat16 g_Bl[256 * LDK_BIG];
__device__ int   g_src[EE], g_dstv[EE], g_col[EE];
__device__ float g_w[EE], g_ew[EE];
__device__ int   g_deg[NN], g_indeg[NN], g_cursor[NN], g_batch[NN];
__device__ float g_dis[NN], g_diag[NN];
__device__ int   g_rowptr[NN + 1];
__device__ int   g_cnt[GG], g_gstart[GG + 1];
__device__ float g_pool[GG * 400];
__device__ int   g_is64;

__device__ __forceinline__ uint32_t smem_to_u32(const void* p) {
    uint32_t a;
    asm("{ .reg .u64 t; cvta.to.shared.u64 t, %1; cvt.u32.u64 %0, t; }" : "=r"(a) : "l"(p));
    return a;
}

// ------------------------- dtype detection + conversion --------------------
__global__ void k_detect(const void* ei) {
    const unsigned* u = (const unsigned*)ei;
    int z = 0;
    for (int i = 0; i < 32; i++)
        if (u[2 * i + 1] == 0u) z++;
    g_is64 = (z >= 16) ? 1 : 0;
}

__global__ void k_cvt_edges(const void* ei) {
    int e = blockIdx.x * blockDim.x + threadIdx.x;
    if (e >= EE) return;
    if (g_is64) {
        const long long* p = (const long long*)ei;
        g_src[e]  = (int)p[e];
        g_dstv[e] = (int)p[EE + e];
    } else {
        const int* p = (const int*)ei;
        g_src[e]  = p[e];
        g_dstv[e] = p[EE + e];
    }
}

__global__ void k_cvt_batch(const void* b) {
    int n = blockIdx.x * blockDim.x + threadIdx.x;
    if (n >= NN) return;
    g_batch[n] = g_is64 ? (int)((const long long*)b)[n] : ((const int*)b)[n];
}

// ------------------------- graph preprocessing ------------------------------
__global__ void k_zero() {
    int i = blockIdx.x * blockDim.x + threadIdx.x;
    if (i < NN) { g_deg[i] = 0; g_indeg[i] = 0; g_cursor[i] = 0; }
    if (i < GG) g_cnt[i] = 0;
}

__global__ void k_deg() {
    int e = blockIdx.x * blockDim.x + threadIdx.x;
    if (e >= EE) return;
    atomicAdd(&g_deg[g_src[e]], 1);
    atomicAdd(&g_indeg[g_dstv[e]], 1);
}

__global__ void k_node(const float* __restrict__ lmax) {
    int n = blockIdx.x * blockDim.x + threadIdx.x;
    if (n >= NN) return;
    int d = g_deg[n];
    g_dis[n]  = (d > 0) ? (1.0f / sqrtf((float)d)) : 0.0f;
    g_diag[n] = 2.0f / lmax[g_batch[n]] - 1.0f;
}

__global__ void k_ew(const float* __restrict__ lmax) {
    int e = blockIdx.x * blockDim.x + threadIdx.x;
    if (e >= EE) return;
    int s = g_src[e], d = g_dstv[e];
    g_w[e] = -g_dis[s] * g_dis[d] * (2.0f / lmax[g_batch[s]]);
}

__global__ void k_scan_rowptr() {
    __shared__ int s[1024];
    __shared__ int carry;
    int tid = threadIdx.x;
    if (tid == 0) carry = 0;
    __syncthreads();
    for (int base = 0; base < NN; base += 1024) {
        int i = base + tid;
        int v = (i < NN) ? g_indeg[i] : 0;
        int xv = v;
        for (int off = 1; off < 1024; off <<= 1) {
            s[tid] = xv; __syncthreads();
            if (tid >= off) xv += s[tid - off];
            __syncthreads();
        }
        int c = carry;
        if (i < NN) g_rowptr[i] = c + xv - v;
        __syncthreads();
        if (tid == 1023) carry = c + xv;
        __syncthreads();
    }
    if (tid == 0) g_rowptr[NN] = EE;
}

__global__ void k_fill() {
    int e = blockIdx.x * blockDim.x + threadIdx.x;
    if (e >= EE) return;
    int d = g_dstv[e];
    int pos = g_rowptr[d] + atomicAdd(&g_cursor[d], 1);
    g_col[pos] = g_src[e];
    g_ew[pos]  = g_w[e];
}

// x -> fp32 g_T[0] slice0 (ld 192) + bf16 hi/lo into A-buffer 0 cols 0-63
__global__ void k_copyx(const float* __restrict__ x) {
    int i = blockIdx.x * blockDim.x + threadIdx.x;
    if (i >= NN * FIN) return;
    int n = i >> 6, f = i & 63;
    float v = x[i];
    g_T[0][(size_t)n * 192 + f] = v;
    __nv_bfloat16 h = __float2bfloat16(v);
    size_t o = (size_t)n * LDK_S + f;
    g_AH[0][o] = h;
    g_AL[0][o] = __float2bfloat16(v - __bfloat162float(h));
}

// zero the K-padding cols [600,640) of both A buffers (after layer-1 layout use)
__global__ void k_padzero() {
    int i = blockIdx.x * blockDim.x + threadIdx.x;
    if (i >= NN * 40) return;
    size_t o = (size_t)(i / 40) * LDK_BIG + 600 + (i % 40);
    __nv_bfloat16 z = __float2bfloat16(0.0f);
    g_AH[0][o] = z; g_AL[0][o] = z;
    g_AH[1][o] = z; g_AL[1][o] = z;
}

// ------------------------- sparse propagation (gather, warp/node) -----------
// out = alpha*(L_gather + diag*h) + beta*slice0 ; writes bf16 hi/lo (+opt fp32)
template <int F, int LD>
__global__ void k_prop(int sel, int srcS, int dstS, float alpha, float beta,
                       int useSub, int writeF32,
                       __nv_bfloat16* __restrict__ Ah, __nv_bfloat16* __restrict__ Al,
                       int aoff, int lda) {
    int w = (blockIdx.x * blockDim.x + threadIdx.x) >> 5;
    if (w >= NN) return;
    int lane = threadIdx.x & 31;
    float* base = g_T[sel];
    const float* hs  = base + srcS * F;
    float*       out = base + dstS * F;
    const float* sub = base;
    constexpr int NJ = (F + 31) / 32;
    float acc[NJ];
#pragma unroll
    for (int j = 0; j < NJ; j++) acc[j] = 0.0f;

    int e = g_rowptr[w], eend = g_rowptr[w + 1];
    for (; e < eend; e++) {
        int   c  = __ldg(&g_col[e]);
        float we = __ldg(&g_ew[e]);
        const float* row = hs + (size_t)c * LD;
#pragma unroll
        for (int j = 0; j < NJ; j++) {
            int f = lane + 32 * j;
            if (f < F) acc[j] += we * row[f];
        }
    }
    float dg = g_diag[w];
    const float* hrow = hs  + (size_t)w * LD;
    float*       orow = out + (size_t)w * LD;
    const float* srow = sub + (size_t)w * LD;
    size_t abase = (size_t)w * lda + aoff;
#pragma unroll
    for (int j = 0; j < NJ; j++) {
        int f = lane + 32 * j;
        if (f < F) {
            float v = alpha * (acc[j] + dg * hrow[f]);
            if (useSub) v += beta * srow[f];
            if (writeF32) orow[f] = v;
            __nv_bfloat16 h = __float2bfloat16(v);
            Ah[abase + f] = h;
            Al[abase + f] = __float2bfloat16(v - __bfloat162float(h));
        }
    }
}

// ------------------------- W -> bf16 hi/lo (transposed, padded 256 x LDK) ---
__global__ void k_cvtB(const float* __restrict__ W, int Kd, int LDK) {
    int k = blockIdx.x * 64 + threadIdx.x;
    int n = blockIdx.y;
    if (k >= LDK) return;
    float v = (n < HH && k < Kd) ? W[(size_t)k * HH + n] : 0.0f;
    __nv_bfloat16 h = __float2bfloat16(v);
    __nv_bfloat16 l = __float2bfloat16(v - __bfloat162float(h));
    size_t o = (size_t)n * LDK + k;
    g_Bh[o] = h;
    g_Bl[o] = l;
}

// ------------------------- HMMA GEMM (mma.sync bf16 3-split, fp32 acc) -----
// C[gm][col] = relu(sum_k A[gm][k]*B[col][k] + bias[col]), col < 200
// BM=128, BN=224, K-chunks of 64; 8 warps = 2(m) x 4(n); cp.async 2-stage pipe.
#define SA_B   144                     // bytes per smem row (72 bf16, conflict-free)
#define OA_H   0
#define OA_L   18432                   // 128*144
#define OB_H   36864
#define OB_L   69120                   // +224*144
#define STG    101376                  // stage size
#define SM_TOT (2 * STG)               // 202752 B

__device__ __forceinline__ void ldsm_x4(uint32_t addr, uint32_t& r0, uint32_t& r1,
                                        uint32_t& r2, uint32_t& r3) {
    asm volatile("ldmatrix.sync.aligned.m8n8.x4.shared.b16 {%0,%1,%2,%3}, [%4];"
                 : "=r"(r0), "=r"(r1), "=r"(r2), "=r"(r3) : "r"(addr));
}
__device__ __forceinline__ void ldsm_x2(uint32_t addr, uint32_t& r0, uint32_t& r1) {
    asm volatile("ldmatrix.sync.aligned.m8n8.x2.shared.b16 {%0,%1}, [%2];"
                 : "=r"(r0), "=r"(r1) : "r"(addr));
}
__device__ __forceinline__ void mma16816(float* c, const uint32_t* a, const uint32_t* b) {
    asm volatile(
        "mma.sync.aligned.m16n8k16.row.col.f32.bf16.bf16.f32 "
        "{%0,%1,%2,%3}, {%4,%5,%6,%7}, {%8,%9}, {%0,%1,%2,%3};"
        : "+f"(c[0]), "+f"(c[1]), "+f"(c[2]), "+f"(c[3])
        : "r"(a[0]), "r"(a[1]), "r"(a[2]), "r"(a[3]), "r"(b[0]), "r"(b[1]));
}
__device__ __forceinline__ void cp16(uint32_t daddr, const void* saddr, uint32_t srcsz) {
    asm volatile("cp.async.cg.shared.global [%0], [%1], 16, %2;"
                 :: "r"(daddr), "l"(saddr), "r"(srcsz) : "memory");
}

__global__ __launch_bounds__(256, 1) void k_gemm_mma(
        const __nv_bfloat16* __restrict__ Ah, const __nv_bfloat16* __restrict__ Al,
        int LDK, int nch, const float* __restrict__ bias, int selC,
        __nv_bfloat16* __restrict__ nAh, __nv_bfloat16* __restrict__ nAl) {
    extern __shared__ char smdyn[];
    uint32_t sb = smem_to_u32(smdyn);
    int tid = threadIdx.x, lane = tid & 31, wid = tid >> 5;
    int m0 = blockIdx.x * 128;
    int warpM = wid >> 2, warpN = wid & 3;
    int mrow0 = warpM * 64;
    int ncol0 = warpN * 56;
    const int ldk8 = LDK >> 3;

    const uint4* GAh = (const uint4*)Ah;
    const uint4* GAl = (const uint4*)Al;
    const uint4* GBh = (const uint4*)g_Bh;
    const uint4* GBl = (const uint4*)g_Bl;

    float acc[4][7][4];
#pragma unroll
    for (int i = 0; i < 4; i++)
#pragma unroll
        for (int j = 0; j < 7; j++)
#pragma unroll
            for (int q = 0; q < 4; q++) acc[i][j][q] = 0.0f;

    // lane-invariant ldmatrix address components
    int rr = lane & 7;
    int aRow = rr + 8 * ((lane >> 3) & 1);
    int aK   = 8 * (lane >> 4);
    int bg   = lane >> 3;
    int bRow = rr + 8 * (bg >> 1);
    int bK   = 8 * (bg & 1);
    int bg2  = bg & 1;

    // precompute per-thread load coordinates
    int lrow = tid >> 3, lcc = tid & 7;     // base: row = lrow + 32*i (A), +32*i (B)

    auto issue_stage = [&](int c, int s) {
        int k8 = c * 8;
        uint32_t sbase = sb + s * STG;
#pragma unroll
        for (int i = 0; i < 4; i++) {       // A: rows lrow+32*i
            int row = lrow + 32 * i;
            int gm = m0 + row;
            int ok = (gm < NN);
            size_t gi = (size_t)(ok ? gm : 0) * ldk8 + k8 + lcc;
            uint32_t d = sbase + OA_H + row * SA_B + lcc * 16;
            cp16(d, GAh + gi, ok ? 16u : 0u);
            cp16(d + (OA_L - OA_H), GAl + gi, ok ? 16u : 0u);
        }
#pragma unroll
        for (int i = 0; i < 7; i++) {       // B: rows lrow+32*i (<224)
            int row = lrow + 32 * i;
            size_t gi = (size_t)row * ldk8 + k8 + lcc;
            uint32_t d = sbase + OB_H + row * SA_B + lcc * 16;
            cp16(d, GBh + gi, 16u);
            cp16(d + (OB_L - OB_H), GBl + gi, 16u);
        }
        asm volatile("cp.async.commit_group;" ::: "memory");
    };

    issue_stage(0, 0);

    for (int c = 0; c < nch; c++) {
        asm volatile("cp.async.wait_group 0;" ::: "memory");
        __syncthreads();
        if (c + 1 < nch) issue_stage(c + 1, (c + 1) & 1);

        uint32_t aH = sb + (c & 1) * STG + OA_H;
        uint32_t aL = sb + (c & 1) * STG + OA_L;
        uint32_t bH = sb + (c & 1) * STG + OB_H;
        uint32_t bL = sb + (c & 1) * STG + OB_L;

#pragma unroll
        for (int ks = 0; ks < 4; ks++) {
            int kel = ks * 16;
            uint32_t bh[7][2], bl[7][2];
#pragma unroll
            for (int p = 0; p < 3; p++) {
                uint32_t boff = (uint32_t)((ncol0 + p * 16 + bRow) * SA_B + (kel + bK) * 2);
                ldsm_x4(bH + boff, bh[2*p][0], bh[2*p][1], bh[2*p+1][0], bh[2*p+1][1]);
                ldsm_x4(bL + boff, bl[2*p][0], bl[2*p][1], bl[2*p+1][0], bl[2*p+1][1]);
            }
            {
                uint32_t boff = (uint32_t)((ncol0 + 48 + rr) * SA_B + (kel + 8 * bg2) * 2);
                ldsm_x2(bH + boff, bh[6][0], bh[6][1]);
                ldsm_x2(bL + boff, bl[6][0], bl[6][1]);
            }
#pragma unroll
            for (int mt = 0; mt < 4; mt++) {
                uint32_t aoff = (uint32_t)((mrow0 + mt * 16 + aRow) * SA_B + (kel + aK) * 2);
                uint32_t ah[4], al[4];
                ldsm_x4(aH + aoff, ah[0], ah[1], ah[2], ah[3]);
                ldsm_x4(aL + aoff, al[0], al[1], al[2], al[3]);
#pragma unroll
                for (int nt = 0; nt < 7; nt++) {
                    mma16816(acc[mt][nt], ah, bh[nt]);
                    mma16816(acc[mt][nt], ah, bl[nt]);
                    mma16816(acc[mt][nt], al, bh[nt]);
                }
            }
        }
        // note: next-iteration wait_group+syncthreads protects buffer reuse
    }

    // epilogue: bias + relu; fp32 into g_T[selC], bf16 hi/lo into next A-buffer
    float* C = g_T[selC];
    int qrow = lane >> 2, qcol = (lane & 3) * 2;
#pragma unroll
    for (int mt = 0; mt < 4; mt++) {
        int row = m0 + mrow0 + mt * 16 + qrow;
#pragma unroll
        for (int nt = 0; nt < 7; nt++) {
            int col = ncol0 + nt * 8 + qcol;
            if (col < HH) {
                float bz0 = __ldg(&bias[col]);
                float bz1 = __ldg(&bias[col + 1]);
#pragma unroll
                for (int half = 0; half < 2; half++) {
                    int r = row + 8 * half;
                    if (r < NN) {
                        float v0 = fmaxf(acc[mt][nt][2 * half]     + bz0, 0.0f);
                        float v1 = fmaxf(acc[mt][nt][2 * half + 1] + bz1, 0.0f);
                        C[(size_t)r * 600 + col]     = v0;
                        C[(size_t)r * 600 + col + 1] = v1;
                        if (nAh) {
                            size_t ab = (size_t)r * LDK_BIG + col;
                            __nv_bfloat16 h0 = __float2bfloat16(v0);
                            __nv_bfloat16 h1 = __float2bfloat16(v1);
                            nAh[ab]     = h0;
                            nAh[ab + 1] = h1;
                            nAl[ab]     = __float2bfloat16(v0 - __bfloat162float(h0));
                            nAl[ab + 1] = __float2bfloat16(v1 - __bfloat162float(h1));
                        }
                    }
                }
            }
        }
    }
}

// ------------------------- pooling + fc + log_softmax -----------------------
__global__ void k_cnt() {
    int n = blockIdx.x * blockDim.x + threadIdx.x;
    if (n >= NN) return;
    atomicAdd(&g_cnt[g_batch[n]], 1);
}

__global__ void k_scan_g() {
    __shared__ int s[GG];
    int tid = threadIdx.x;
    int v = g_cnt[tid];
    int xv = v;
    for (int off = 1; off < GG; off <<= 1) {
        s[tid] = xv; __syncthreads();
        if (tid >= off) xv += s[tid - off];
        __syncthreads();
    }
    g_gstart[tid] = xv - v;
    if (tid == GG - 1) g_gstart[GG] = xv;
}

__global__ void k_pool() {
    int g = blockIdx.x, f = threadIdx.x;
    if (f >= HH) return;
    int s = g_gstart[g], e = g_gstart[g + 1];
    float sum = 0.0f, mx = -3.4e38f;
    const float* base = g_T[0];
    for (int n = s; n < e; n++) {
        float v = base[(size_t)n * 600 + f];
        sum += v;
        mx = fmaxf(mx, v);
    }
    float c = (float)(e - s);
    g_pool[g * 400 + f]      = sum / fmaxf(c, 1.0f);
    g_pool[g * 400 + HH + f] = mx;
}

__global__ void k_fc(const float* __restrict__ fw, const float* __restrict__ fb,
                     float* __restrict__ out) {
    int g = blockIdx.x * blockDim.x + threadIdx.x;
    if (g >= GG) return;
    float z0 = fb[0], z1 = fb[1];
    const float* p = &g_pool[g * 400];
    for (int j = 0; j < 400; j++) {
        float v = p[j];
        z0 += v * fw[2 * j];
        z1 += v * fw[2 * j + 1];
    }
    float m = fmaxf(z0, z1);
    float l = m + logf(expf(z0 - m) + expf(z1 - m));
    out[2 * g]     = z0 - l;
    out[2 * g + 1] = z1 - l;
}

// ------------------------- launch ------------------------------------------
extern "C" void kernel_launch(void* const* d_in, const int* in_sizes, int n_in,
                              void* d_out, int out_size) {
    const float* x     = (const float*)d_in[0];
    const void*  ei    = d_in[1];
    const void*  batch = d_in[2];
    const float* lmax  = (const float*)d_in[3];
    const float* W1 = (const float*)d_in[4];  const float* b1 = (const float*)d_in[5];
    const float* W2 = (const float*)d_in[6];  const float* b2 = (const float*)d_in[7];
    const float* W3 = (const float*)d_in[8];  const float* b3 = (const float*)d_in[9];
    const float* W4 = (const float*)d_in[10]; const float* b4 = (const float*)d_in[11];
    const float* fw = (const float*)d_in[12]; const float* fb = (const float*)d_in[13];
    float* out = (float*)d_out;

    cudaFuncSetAttribute(k_gemm_mma, cudaFuncAttributeMaxDynamicSharedMemorySize, SM_TOT);

    const int TB = 256;
    int nbN = (NN + TB - 1) / TB;
    int nbE = (EE + TB - 1) / TB;

    __nv_bfloat16 *AH0, *AL0, *AH1, *AL1;
    cudaGetSymbolAddress((void**)&AH0, g_AH);  AH1 = AH0 + (size_t)NN * LDK_BIG;
    cudaGetSymbolAddress((void**)&AL0, g_AL);  AL1 = AL0 + (size_t)NN * LDK_BIG;

    k_detect<<<1, 1>>>(ei);
    k_zero<<<nbN, TB>>>();
    k_cvt_edges<<<nbE, TB>>>(ei);
    k_cvt_batch<<<nbN, TB>>>(batch);
    k_deg<<<nbE, TB>>>();
    k_node<<<nbN, TB>>>(lmax);
    k_ew<<<nbE, TB>>>(lmax);
    k_scan_rowptr<<<1, 1024>>>();
    k_fill<<<nbE, TB>>>();
    k_copyx<<<(NN * FIN + TB - 1) / TB, TB>>>(x);

    int propBlocks = (NN * 32 + TB - 1) / TB;   // one warp per node
    int gemmBlocks = (NN + 127) / 128;          // 391
    dim3 cvtSB((LDK_S + 63) / 64, 256), cvtBB((LDK_BIG + 63) / 64, 256);

    // layer 1: A-buf0 (ld 192) -> GEMM -> g_T[1] + A-buf1 cols 0-199
    k_prop<64, 192><<<propBlocks, TB>>>(0, 0, 1, 1.0f, 0.0f, 0, 1, AH0, AL0, 64, LDK_S);
    k_prop<64, 192><<<propBlocks, TB>>>(0, 1, 2, 2.0f, -1.0f, 1, 0, AH0, AL0, 128, LDK_S);
    k_cvtB<<<cvtSB, 64>>>(W1, 192, LDK_S);
    k_gemm_mma<<<gemmBlocks, 256, SM_TOT>>>(AH0, AL0, LDK_S, 3, b1, 1, AH1, AL1);
    k_padzero<<<(NN * 40 + TB - 1) / TB, TB>>>();

    // layer 2: A-buf1 -> g_T[0] + A-buf0
    k_prop<200, 600><<<propBlocks, TB>>>(1, 0, 1, 1.0f, 0.0f, 0, 1, AH1, AL1, 200, LDK_BIG);
    k_prop<200, 600><<<propBlocks, TB>>>(1, 1, 2, 2.0f, -1.0f, 1, 0, AH1, AL1, 400, LDK_BIG);
    k_cvtB<<<cvtBB, 64>>>(W2, 600, LDK_BIG);
    k_gemm_mma<<<gemmBlocks, 256, SM_TOT>>>(AH1, AL1, LDK_BIG, 10, b2, 0, AH0, AL0);

    // layer 3: A-buf0 -> g_T[1] + A-buf1
    k_prop<200, 600><<<propBlocks, TB>>>(0, 0, 1, 1.0f, 0.0f, 0, 1, AH0, AL0, 200, LDK_BIG);
    k_prop<200, 600><<<propBlocks, TB>>>(0, 1, 2, 2.0f, -1.0f, 1, 0, AH0, AL0, 400, LDK_BIG);
    k_cvtB<<<cvtBB, 64>>>(W3, 600, LDK_BIG);
    k_gemm_mma<<<gemmBlocks, 256, SM_TOT>>>(AH0, AL0, LDK_BIG, 10, b3, 1, AH1, AL1);

    // layer 4: A-buf1 -> g_T[0] (no next A-buffer)
    k_prop<200, 600><<<propBlocks, TB>>>(1, 0, 1, 1.0f, 0.0f, 0, 1, AH1, AL1, 200, LDK_BIG);
    k_prop<200, 600><<<propBlocks, TB>>>(1, 1, 2, 2.0f, -1.0f, 1, 0, AH1, AL1, 400, LDK_BIG);
    k_cvtB<<<cvtBB, 64>>>(W4, 600, LDK_BIG);
    k_gemm_mma<<<gemmBlocks, 256, SM_TOT>>>(AH1, AL1, LDK_BIG, 10, b4, 0, nullptr, nullptr);

    // pooling over sorted batch, then fc + log_softmax
    k_cnt<<<nbN, TB>>>();
    k_scan_g<<<1, GG>>>();
    k_pool<<<GG, TB>>>();
    k_fc<<<1, GG>>>(fw, fb, out);
}

// round 9
// speedup vs baseline: 1.8010x; 1.0704x over previous
#include <cuda_runtime.h>
#include <cuda_bf16.h>
#include <math.h>
#include <stdint.h>

#define NN  50000
#define EE  800000
#define FIN 64
#define HH  200
#define GG  256

#define LDK_BIG 640   // 3*200 padded to /64
#define LDK_S   192   // 3*64
#define GEMM_GRID 152 // persistent CTAs (GB300: 152 SMs)

// ------------------------- scratch (device globals; no allocation) ---------
__device__ __align__(256) float g_T[2][(size_t)NN * 600];   // ping-pong fp32 [N][3F]
__device__ __align__(256) __nv_bfloat16 g_AH[2][(size_t)NN * LDK_BIG];
__device__ __align__(256) __nv_bfloat16 g_AL[2][(size_t)NN * LDK_BIG];
__device__ __align__(256) __nv_bfloat16 g_Bh[256 * LDK_BIG];
__device__ __align__(256) __nv_bfloat16 g_Bl[256 * LDK_BIG];
__device__ int   g_src[EE], g_dstv[EE];
__device__ int2  g_cw[EE];                 // packed (col, weight-bits) CSR payload
__device__ float g_w[EE];
__device__ int   g_deg[NN], g_indeg[NN], g_cursor[NN], g_batch[NN];
__device__ float g_dis[NN], g_diag[NN];
__device__ int   g_rowptr[NN + 1];
__device__ int   g_bsum[64], g_boff[64];
__device__ int   g_cnt[GG], g_gstart[GG + 1];
__device__ float g_pool[GG * 400];
__device__ int   g_is64;

__device__ __forceinline__ uint32_t smem_to_u32(const void* p) {
    uint32_t a;
    asm("{ .reg .u64 t; cvta.to.shared.u64 t, %1; cvt.u32.u64 %0, t; }" : "=r"(a) : "l"(p));
    return a;
}

// ------------------------- init: zero counters + dtype detect ---------------
__global__ void k_init(const void* ei) {
    int i = blockIdx.x * blockDim.x + threadIdx.x;
    if (i < NN) { g_deg[i] = 0; g_indeg[i] = 0; g_cursor[i] = 0; }
    if (i < GG) g_cnt[i] = 0;
    if (i == 0) {
        const unsigned* u = (const unsigned*)ei;
        int z = 0;
        for (int j = 0; j < 32; j++)
            if (u[2 * j + 1] == 0u) z++;
        g_is64 = (z >= 16) ? 1 : 0;   // int64 little-endian: high words all zero
    }
}

// ------------------------- fused conversion: edges + batch + x copy ---------
__global__ void k_cvt_all(const void* ei, const void* b, const float* __restrict__ x) {
    int stride = gridDim.x * blockDim.x;
    int t0 = blockIdx.x * blockDim.x + threadIdx.x;
    int is64 = g_is64;
    if (is64) {
        const long long* p = (const long long*)ei;
        for (int e = t0; e < EE; e += stride) {
            g_src[e]  = (int)p[e];
            g_dstv[e] = (int)p[EE + e];
        }
        const long long* pb = (const long long*)b;
        for (int n = t0; n < NN; n += stride) g_batch[n] = (int)pb[n];
    } else {
        const int* p = (const int*)ei;
        for (int e = t0; e < EE; e += stride) {
            g_src[e]  = p[e];
            g_dstv[e] = p[EE + e];
        }
        const int* pb = (const int*)b;
        for (int n = t0; n < NN; n += stride) g_batch[n] = pb[n];
    }
    for (int i = t0; i < NN * FIN; i += stride) {
        int n = i >> 6, f = i & 63;
        float v = x[i];
        g_T[0][(size_t)n * 192 + f] = v;
        __nv_bfloat16 h = __float2bfloat16(v);
        size_t o = (size_t)n * LDK_S + f;
        g_AH[0][o] = h;
        g_AL[0][o] = __float2bfloat16(v - __bfloat162float(h));
    }
}

// ------------------------- graph preprocessing ------------------------------
__global__ void k_deg() {
    int e = blockIdx.x * blockDim.x + threadIdx.x;
    if (e >= EE) return;
    atomicAdd(&g_deg[g_src[e]], 1);
    atomicAdd(&g_indeg[g_dstv[e]], 1);
}

__global__ void k_node(const float* __restrict__ lmax) {
    int n = blockIdx.x * blockDim.x + threadIdx.x;
    if (n >= NN) return;
    int d = g_deg[n];
    g_dis[n]  = (d > 0) ? (1.0f / sqrtf((float)d)) : 0.0f;
    g_diag[n] = 2.0f / lmax[g_batch[n]] - 1.0f;
    atomicAdd(&g_cnt[g_batch[n]], 1);   // fused pooling count
}

__global__ void k_ew(const float* __restrict__ lmax) {
    int e = blockIdx.x * blockDim.x + threadIdx.x;
    if (e >= EE) return;
    int s = g_src[e], d = g_dstv[e];
    g_w[e] = -g_dis[s] * g_dis[d] * (2.0f / lmax[g_batch[s]]);
}

// multi-block exclusive scan of indeg -> rowptr (3 passes)
__global__ void k_scan1() {
    __shared__ int s[1024];
    int tid = threadIdx.x;
    int i = blockIdx.x * 1024 + tid;
    int v = (i < NN) ? g_indeg[i] : 0;
    int xv = v;
    for (int off = 1; off < 1024; off <<= 1) {
        s[tid] = xv; __syncthreads();
        if (tid >= off) xv += s[tid - off];
        __syncthreads();
    }
    if (i < NN) g_rowptr[i] = xv - v;        // exclusive, pre-offset
    if (tid == 1023) g_bsum[blockIdx.x] = xv;
}
__global__ void k_scan2(int nb) {
    __shared__ int s[64];
    int tid = threadIdx.x;
    int v = (tid < nb) ? g_bsum[tid] : 0;
    int xv = v;
    for (int off = 1; off < 64; off <<= 1) {
        s[tid] = xv; __syncthreads();
        if (tid >= off) xv += s[tid - off];
        __syncthreads();
    }
    g_boff[tid] = xv - v;
}
__global__ void k_scan3() {
    int i = blockIdx.x * 1024 + threadIdx.x;
    if (i < NN) g_rowptr[i] += g_boff[blockIdx.x];
    if (i == 0) g_rowptr[NN] = EE;
}

__global__ void k_fill() {
    int e = blockIdx.x * blockDim.x + threadIdx.x;
    if (e >= EE) return;
    int d = g_dstv[e];
    int pos = g_rowptr[d] + atomicAdd(&g_cursor[d], 1);
    g_cw[pos] = make_int2(g_src[e], __float_as_int(g_w[e]));
}

// zero K-pad cols [600,640) of both A buffers (after layer-1 192-layout use)
__global__ void k_padzero() {
    int i = blockIdx.x * blockDim.x + threadIdx.x;
    if (i >= NN * 40) return;
    size_t o = (size_t)(i / 40) * LDK_BIG + 600 + (i % 40);
    __nv_bfloat16 z = __float2bfloat16(0.0f);
    g_AH[0][o] = z; g_AL[0][o] = z;
    g_AH[1][o] = z; g_AL[1][o] = z;
}

// ------------------------- sparse propagation (gather, warp/node) -----------
// out = alpha*(L_gather + diag*h) + beta*slice0 ; writes bf16 hi/lo (+opt fp32)
template <int F, int LD>
__global__ void k_prop(int sel, int srcS, int dstS, float alpha, float beta,
                       int useSub, int writeF32,
                       __nv_bfloat16* __restrict__ Ah, __nv_bfloat16* __restrict__ Al,
                       int aoff, int lda) {
    int w = (blockIdx.x * blockDim.x + threadIdx.x) >> 5;
    if (w >= NN) return;
    int lane = threadIdx.x & 31;
    float* base = g_T[sel];
    const float* hs  = base + srcS * F;
    float*       out = base + dstS * F;
    const float* sub = base;
    constexpr int NJ = (F + 31) / 32;
    float acc[NJ];
#pragma unroll
    for (int j = 0; j < NJ; j++) acc[j] = 0.0f;

    int e = g_rowptr[w], eend = g_rowptr[w + 1];
#pragma unroll 2
    for (; e < eend; e++) {
        int2 cw = __ldg(&g_cw[e]);
        float we = __int_as_float(cw.y);
        const float* row = hs + (size_t)cw.x * LD;
#pragma unroll
        for (int j = 0; j < NJ; j++) {
            int f = lane + 32 * j;
            if (f < F) acc[j] += we * row[f];
        }
    }
    float dg = g_diag[w];
    const float* hrow = hs  + (size_t)w * LD;
    float*       orow = out + (size_t)w * LD;
    const float* srow = sub + (size_t)w * LD;
    size_t abase = (size_t)w * lda + aoff;
#pragma unroll
    for (int j = 0; j < NJ; j++) {
        int f = lane + 32 * j;
        if (f < F) {
            float v = alpha * (acc[j] + dg * hrow[f]);
            if (useSub) v += beta * srow[f];
            if (writeF32) orow[f] = v;
            __nv_bfloat16 h = __float2bfloat16(v);
            Ah[abase + f] = h;
            Al[abase + f] = __float2bfloat16(v - __bfloat162float(h));
        }
    }
}

// ------------------------- W -> bf16 hi/lo (transposed, padded 256 x LDK) ---
__global__ void k_cvtB(const float* __restrict__ W, int Kd, int LDK) {
    int k = blockIdx.x * 64 + threadIdx.x;
    int n = blockIdx.y;
    if (k >= LDK) return;
    float v = (n < HH && k < Kd) ? W[(size_t)k * HH + n] : 0.0f;
    __nv_bfloat16 h = __float2bfloat16(v);
    __nv_bfloat16 l = __float2bfloat16(v - __bfloat162float(h));
    size_t o = (size_t)n * LDK + k;
    g_Bh[o] = h;
    g_Bl[o] = l;
}

// ------------------------- HMMA GEMM (mma.sync bf16 3-split, fp32 acc) -----
// Persistent: GEMM_GRID CTAs loop M-tiles; cp.async pipeline threaded across
// tiles so epilogue is hidden behind the next tile's loads.
#define SA_B   144                     // bytes per smem row (72 bf16, conflict-free)
#define OA_H   0
#define OA_L   18432                   // 128*144
#define OB_H   36864
#define OB_L   69120                   // +224*144
#define STG    101376                  // stage size
#define SM_TOT (2 * STG)               // 202752 B

__device__ __forceinline__ void ldsm_x4(uint32_t addr, uint32_t& r0, uint32_t& r1,
                                        uint32_t& r2, uint32_t& r3) {
    asm volatile("ldmatrix.sync.aligned.m8n8.x4.shared.b16 {%0,%1,%2,%3}, [%4];"
                 : "=r"(r0), "=r"(r1), "=r"(r2), "=r"(r3) : "r"(addr));
}
__device__ __forceinline__ void ldsm_x2(uint32_t addr, uint32_t& r0, uint32_t& r1) {
    asm volatile("ldmatrix.sync.aligned.m8n8.x2.shared.b16 {%0,%1}, [%2];"
                 : "=r"(r0), "=r"(r1) : "r"(addr));
}
__device__ __forceinline__ void mma16816(float* c, const uint32_t* a, const uint32_t* b) {
    asm volatile(
        "mma.sync.aligned.m16n8k16.row.col.f32.bf16.bf16.f32 "
        "{%0,%1,%2,%3}, {%4,%5,%6,%7}, {%8,%9}, {%0,%1,%2,%3};"
        : "+f"(c[0]), "+f"(c[1]), "+f"(c[2]), "+f"(c[3])
        : "r"(a[0]), "r"(a[1]), "r"(a[2]), "r"(a[3]), "r"(b[0]), "r"(b[1]));
}
__device__ __forceinline__ void cp16(uint32_t daddr, const void* saddr, uint32_t srcsz) {
    asm volatile("cp.async.cg.shared.global [%0], [%1], 16, %2;"
                 :: "r"(daddr), "l"(saddr), "r"(srcsz) : "memory");
}

__global__ __launch_bounds__(256, 1) void k_gemm_mma(
        const __nv_bfloat16* __restrict__ Ah, const __nv_bfloat16* __restrict__ Al,
        int LDK, int nch, const float* __restrict__ bias, int selC,
        __nv_bfloat16* __restrict__ nAh, __nv_bfloat16* __restrict__ nAl) {
    extern __shared__ char smdyn[];
    uint32_t sb = smem_to_u32(smdyn);
    int tid = threadIdx.x, lane = tid & 31, wid = tid >> 5;
    int warpM = wid >> 2, warpN = wid & 3;
    int mrow0 = warpM * 64;
    int ncol0 = warpN * 56;
    const int ldk8 = LDK >> 3;
    const int ntiles = (NN + 127) >> 7;   // 391

    const uint4* GAh = (const uint4*)Ah;
    const uint4* GAl = (const uint4*)Al;
    const uint4* GBh = (const uint4*)g_Bh;
    const uint4* GBl = (const uint4*)g_Bl;

    // lane-invariant ldmatrix address components
    int rr = lane & 7;
    int aRow = rr + 8 * ((lane >> 3) & 1);
    int aK   = 8 * (lane >> 4);
    int bg   = lane >> 3;
    int bRow = rr + 8 * (bg >> 1);
    int bK   = 8 * (bg & 1);
    int bg2  = bg & 1;

    int lrow = tid >> 3, lcc = tid & 7;   // per-thread load coordinates

    auto issue_stage = [&](int m0, int c, int s) {
        int k8 = c * 8;
        uint32_t sbase = sb + s * STG;
#pragma unroll
        for (int i = 0; i < 4; i++) {       // A: rows lrow+32*i
            int row = lrow + 32 * i;
            int gm = m0 + row;
            int ok = (gm < NN);
            size_t gi = (size_t)(ok ? gm : 0) * ldk8 + k8 + lcc;
            uint32_t d = sbase + OA_H + row * SA_B + lcc * 16;
            cp16(d, GAh + gi, ok ? 16u : 0u);
            cp16(d + (OA_L - OA_H), GAl + gi, ok ? 16u : 0u);
        }
#pragma unroll
        for (int i = 0; i < 7; i++) {       // B: rows lrow+32*i (<224)
            int row = lrow + 32 * i;
            size_t gi = (size_t)row * ldk8 + k8 + lcc;
            uint32_t d = sbase + OB_H + row * SA_B + lcc * 16;
            cp16(d, GBh + gi, 16u);
            cp16(d + (OB_L - OB_H), GBl + gi, 16u);
        }
        asm volatile("cp.async.commit_group;" ::: "memory");
    };

    int p = 0;                               // compute-buffer parity
    if ((int)blockIdx.x < ntiles) issue_stage(blockIdx.x * 128, 0, 0);

    for (int t = blockIdx.x; t < ntiles; t += gridDim.x) {
        int m0 = t * 128;

        float acc[4][7][4];
#pragma unroll
        for (int i = 0; i < 4; i++)
#pragma unroll
            for (int j = 0; j < 7; j++)
#pragma unroll
                for (int q = 0; q < 4; q++) acc[i][j][q] = 0.0f;

        for (int c = 0; c < nch; c++) {
            asm volatile("cp.async.wait_group 0;" ::: "memory");
            __syncthreads();
            if (c + 1 < nch)
                issue_stage(m0, c + 1, p ^ 1);
            else if (t + (int)gridDim.x < ntiles)
                issue_stage((t + gridDim.x) * 128, 0, p ^ 1);

            uint32_t aH = sb + p * STG + OA_H;
            uint32_t aL = sb + p * STG + OA_L;
            uint32_t bH = sb + p * STG + OB_H;
            uint32_t bL = sb + p * STG + OB_L;

#pragma unroll
            for (int ks = 0; ks < 4; ks++) {
                int kel = ks * 16;
                uint32_t bh[7][2], bl[7][2];
#pragma unroll
                for (int q = 0; q < 3; q++) {
                    uint32_t boff = (uint32_t)((ncol0 + q * 16 + bRow) * SA_B + (kel + bK) * 2);
                    ldsm_x4(bH + boff, bh[2*q][0], bh[2*q][1], bh[2*q+1][0], bh[2*q+1][1]);
                    ldsm_x4(bL + boff, bl[2*q][0], bl[2*q][1], bl[2*q+1][0], bl[2*q+1][1]);
                }
                {
                    uint32_t boff = (uint32_t)((ncol0 + 48 + rr) * SA_B + (kel + 8 * bg2) * 2);
                    ldsm_x2(bH + boff, bh[6][0], bh[6][1]);
                    ldsm_x2(bL + boff, bl[6][0], bl[6][1]);
                }
#pragma unroll
                for (int mt = 0; mt < 4; mt++) {
                    uint32_t aoff = (uint32_t)((mrow0 + mt * 16 + aRow) * SA_B + (kel + aK) * 2);
                    uint32_t ah[4], al[4];
                    ldsm_x4(aH + aoff, ah[0], ah[1], ah[2], ah[3]);
                    ldsm_x4(aL + aoff, al[0], al[1], al[2], al[3]);
#pragma unroll
                    for (int nt = 0; nt < 7; nt++) {
                        mma16816(acc[mt][nt], ah, bh[nt]);
                        mma16816(acc[mt][nt], ah, bl[nt]);
                        mma16816(acc[mt][nt], al, bh[nt]);
                    }
                }
            }
            p ^= 1;
        }

        // epilogue: bias + relu; fp32 into g_T[selC], bf16 hi/lo into next A-buf
        float* C = g_T[selC];
        int qrow = lane >> 2, qcol = (lane & 3) * 2;
#pragma unroll
        for (int mt = 0; mt < 4; mt++) {
            int row = m0 + mrow0 + mt * 16 + qrow;
#pragma unroll
            for (int nt = 0; nt < 7; nt++) {
                int col = ncol0 + nt * 8 + qcol;
                if (col < HH) {
                    float bz0 = __ldg(&bias[col]);
                    float bz1 = __ldg(&bias[col + 1]);
#pragma unroll
                    for (int half = 0; half < 2; half++) {
                        int r = row + 8 * half;
                        if (r < NN) {
                            float v0 = fmaxf(acc[mt][nt][2 * half]     + bz0, 0.0f);
                            float v1 = fmaxf(acc[mt][nt][2 * half + 1] + bz1, 0.0f);
                            C[(size_t)r * 600 + col]     = v0;
                            C[(size_t)r * 600 + col + 1] = v1;
                            if (nAh) {
                                size_t ab = (size_t)r * LDK_BIG + col;
                                __nv_bfloat16 h0 = __float2bfloat16(v0);
                                __nv_bfloat16 h1 = __float2bfloat16(v1);
                                nAh[ab]     = h0;
                                nAh[ab + 1] = h1;
                                nAl[ab]     = __float2bfloat16(v0 - __bfloat162float(h0));
                                nAl[ab + 1] = __float2bfloat16(v1 - __bfloat162float(h1));
                            }
                        }
                    }
                }
            }
        }
    }
}

// ------------------------- pooling + fc + log_softmax -----------------------
__global__ void k_scan_g() {
    __shared__ int s[GG];
    int tid = threadIdx.x;
    int v = g_cnt[tid];
    int xv = v;
    for (int off = 1; off < GG; off <<= 1) {
        s[tid] = xv; __syncthreads();
        if (tid >= off) xv += s[tid - off];
        __syncthreads();
    }
    g_gstart[tid] = xv - v;
    if (tid == GG - 1) g_gstart[GG] = xv;
}

__global__ void k_pool() {
    int g = blockIdx.x, f = threadIdx.x;
    if (f >= HH) return;
    int s = g_gstart[g], e = g_gstart[g + 1];
    float sum = 0.0f, mx = -3.4e38f;
    const float* base = g_T[0];
    for (int n = s; n < e; n++) {
        float v = base[(size_t)n * 600 + f];
        sum += v;
        mx = fmaxf(mx, v);
    }
    float c = (float)(e - s);
    g_pool[g * 400 + f]      = sum / fmaxf(c, 1.0f);
    g_pool[g * 400 + HH + f] = mx;
}

__global__ void k_fc(const float* __restrict__ fw, const float* __restrict__ fb,
                     float* __restrict__ out) {
    int g = blockIdx.x * blockDim.x + threadIdx.x;
    if (g >= GG) return;
    float z0 = fb[0], z1 = fb[1];
    const float* p = &g_pool[g * 400];
    for (int j = 0; j < 400; j++) {
        float v = p[j];
        z0 += v * fw[2 * j];
        z1 += v * fw[2 * j + 1];
    }
    float m = fmaxf(z0, z1);
    float l = m + logf(expf(z0 - m) + expf(z1 - m));
    out[2 * g]     = z0 - l;
    out[2 * g + 1] = z1 - l;
}

// ------------------------- launch ------------------------------------------
extern "C" void kernel_launch(void* const* d_in, const int* in_sizes, int n_in,
                              void* d_out, int out_size) {
    const float* x     = (const float*)d_in[0];
    const void*  ei    = d_in[1];
    const void*  batch = d_in[2];
    const float* lmax  = (const float*)d_in[3];
    const float* W1 = (const float*)d_in[4];  const float* b1 = (const float*)d_in[5];
    const float* W2 = (const float*)d_in[6];  const float* b2 = (const float*)d_in[7];
    const float* W3 = (const float*)d_in[8];  const float* b3 = (const float*)d_in[9];
    const float* W4 = (const float*)d_in[10]; const float* b4 = (const float*)d_in[11];
    const float* fw = (const float*)d_in[12]; const float* fb = (const float*)d_in[13];
    float* out = (float*)d_out;

    cudaFuncSetAttribute(k_gemm_mma, cudaFuncAttributeMaxDynamicSharedMemorySize, SM_TOT);

    const int TB = 256;
    int nbN = (NN + TB - 1) / TB;
    int nbE = (EE + TB - 1) / TB;
    int nbS = (NN + 1023) / 1024;   // 49 scan blocks

    __nv_bfloat16 *AH0, *AL0, *AH1, *AL1;
    cudaGetSymbolAddress((void**)&AH0, g_AH);  AH1 = AH0 + (size_t)NN * LDK_BIG;
    cudaGetSymbolAddress((void**)&AL0, g_AL);  AL1 = AL0 + (size_t)NN * LDK_BIG;

    k_init<<<nbN, TB>>>(ei);
    k_cvt_all<<<nbE, TB>>>(ei, batch, x);
    k_deg<<<nbE, TB>>>();
    k_node<<<nbN, TB>>>(lmax);
    k_ew<<<nbE, TB>>>(lmax);
    k_scan1<<<nbS, 1024>>>();
    k_scan2<<<1, 64>>>(nbS);
    k_scan3<<<nbS, 1024>>>();
    k_fill<<<nbE, TB>>>();

    int propBlocks = (NN * 32 + TB - 1) / TB;   // one warp per node
    dim3 cvtSB((LDK_S + 63) / 64, 256), cvtBB((LDK_BIG + 63) / 64, 256);

    // layer 1: A-buf0 (ld 192) -> GEMM -> g_T[1] + A-buf1 cols 0-199
    k_prop<64, 192><<<propBlocks, TB>>>(0, 0, 1, 1.0f, 0.0f, 0, 1, AH0, AL0, 64, LDK_S);
    k_prop<64, 192><<<propBlocks, TB>>>(0, 1, 2, 2.0f, -1.0f, 1, 0, AH0, AL0, 128, LDK_S);
    k_cvtB<<<cvtSB, 64>>>(W1, 192, LDK_S);
    k_gemm_mma<<<GEMM_GRID, 256, SM_TOT>>>(AH0, AL0, LDK_S, 3, b1, 1, AH1, AL1);
    k_padzero<<<(NN * 40 + TB - 1) / TB, TB>>>();

    // layer 2: A-buf1 -> g_T[0] + A-buf0
    k_prop<200, 600><<<propBlocks, TB>>>(1, 0, 1, 1.0f, 0.0f, 0, 1, AH1, AL1, 200, LDK_BIG);
    k_prop<200, 600><<<propBlocks, TB>>>(1, 1, 2, 2.0f, -1.0f, 1, 0, AH1, AL1, 400, LDK_BIG);
    k_cvtB<<<cvtBB, 64>>>(W2, 600, LDK_BIG);
    k_gemm_mma<<<GEMM_GRID, 256, SM_TOT>>>(AH1, AL1, LDK_BIG, 10, b2, 0, AH0, AL0);

    // layer 3: A-buf0 -> g_T[1] + A-buf1
    k_prop<200, 600><<<propBlocks, TB>>>(0, 0, 1, 1.0f, 0.0f, 0, 1, AH0, AL0, 200, LDK_BIG);
    k_prop<200, 600><<<propBlocks, TB>>>(0, 1, 2, 2.0f, -1.0f, 1, 0, AH0, AL0, 400, LDK_BIG);
    k_cvtB<<<cvtBB, 64>>>(W3, 600, LDK_BIG);
    k_gemm_mma<<<GEMM_GRID, 256, SM_TOT>>>(AH0, AL0, LDK_BIG, 10, b3, 1, AH1, AL1);

    // layer 4: A-buf1 -> g_T[0] (no next A-buffer)
    k_prop<200, 600><<<propBlocks, TB>>>(1, 0, 1, 1.0f, 0.0f, 0, 1, AH1, AL1, 200, LDK_BIG);
    k_prop<200, 600><<<propBlocks, TB>>>(1, 1, 2, 2.0f, -1.0f, 1, 0, AH1, AL1, 400, LDK_BIG);
    k_cvtB<<<cvtBB, 64>>>(W4, 600, LDK_BIG);
    k_gemm_mma<<<GEMM_GRID, 256, SM_TOT>>>(AH1, AL1, LDK_BIG, 10, b4, 0, nullptr, nullptr);

    // pooling over sorted batch, then fc + log_softmax
    k_scan_g<<<1, GG>>>();
    k_pool<<<GG, TB>>>();
    k_fc<<<1, GG>>>(fw, fb, out);
}

// round 11
// speedup vs baseline: 1.8790x; 1.0433x over previous
#include <cuda_runtime.h>
#include <cuda_bf16.h>
#include <math.h>
#include <stdint.h>

#define NN  50000
#define EE  800000
#define FIN 64
#define HH  200
#define GG  256

#define LDK_BIG 640   // 3*200 padded to /64
#define LDK_S   192   // 3*64
#define GEMM_GRID 152 // persistent CTAs (GB300: 152 SMs)

// ------------------------- scratch (device globals; no allocation) ---------
__device__ __align__(256) float g_T[2][(size_t)NN * 600];   // ping-pong fp32 [N][3F]
__device__ __align__(256) __nv_bfloat16 g_AH[2][(size_t)NN * LDK_BIG];
__device__ __align__(256) __nv_bfloat16 g_AL[2][(size_t)NN * LDK_BIG];
__device__ __align__(256) __nv_bfloat16 g_Bh[256 * LDK_BIG];
__device__ __align__(256) __nv_bfloat16 g_Bl[256 * LDK_BIG];
__device__ int   g_src[EE], g_dstv[EE];
__device__ int2  g_cw[EE];                 // packed (col, weight-bits) CSR payload
__device__ int   g_deg[NN], g_indeg[NN], g_cursor[NN], g_batch[NN];
__device__ float g_dis[NN], g_diag[NN];
__device__ int   g_rowptr[NN + 1];
__device__ int   g_bsum[64], g_boff[64];
__device__ int   g_cnt[GG], g_gstart[GG + 1];
__device__ float g_pool[GG * 400];
__device__ int   g_is64;

__device__ __forceinline__ uint32_t smem_to_u32(const void* p) {
    uint32_t a;
    asm("{ .reg .u64 t; cvta.to.shared.u64 t, %1; cvt.u32.u64 %0, t; }" : "=r"(a) : "l"(p));
    return a;
}

// ------------------------- init: zero counters + dtype detect ---------------
__global__ void k_init(const void* ei) {
    int i = blockIdx.x * blockDim.x + threadIdx.x;
    if (i < NN) { g_deg[i] = 0; g_indeg[i] = 0; g_cursor[i] = 0; }
    if (i < GG) g_cnt[i] = 0;
    if (i == 0) {
        const unsigned* u = (const unsigned*)ei;
        int z = 0;
        for (int j = 0; j < 32; j++)
            if (u[2 * j + 1] == 0u) z++;
        g_is64 = (z >= 16) ? 1 : 0;   // int64 little-endian: high words all zero
    }
}

// ---------- fused: edge/batch convert + degree atomics + x copy -------------
__global__ void k_cvt_all(const void* ei, const void* b, const float* __restrict__ x) {
    int stride = gridDim.x * blockDim.x;
    int t0 = blockIdx.x * blockDim.x + threadIdx.x;
    int is64 = g_is64;
    if (is64) {
        const long long* p = (const long long*)ei;
        for (int e = t0; e < EE; e += stride) {
            int s = (int)p[e], d = (int)p[EE + e];
            g_src[e] = s; g_dstv[e] = d;
            atomicAdd(&g_deg[s], 1);
            atomicAdd(&g_indeg[d], 1);
        }
        const long long* pb = (const long long*)b;
        for (int n = t0; n < NN; n += stride) g_batch[n] = (int)pb[n];
    } else {
        const int* p = (const int*)ei;
        for (int e = t0; e < EE; e += stride) {
            int s = p[e], d = p[EE + e];
            g_src[e] = s; g_dstv[e] = d;
            atomicAdd(&g_deg[s], 1);
            atomicAdd(&g_indeg[d], 1);
        }
        const int* pb = (const int*)b;
        for (int n = t0; n < NN; n += stride) g_batch[n] = pb[n];
    }
    for (int i = t0; i < NN * FIN; i += stride) {
        int n = i >> 6, f = i & 63;
        float v = x[i];
        g_T[0][(size_t)n * 192 + f] = v;
        __nv_bfloat16 h = __float2bfloat16(v);
        size_t o = (size_t)n * LDK_S + f;
        g_AH[0][o] = h;
        g_AL[0][o] = __float2bfloat16(v - __bfloat162float(h));
    }
}

__global__ void k_node(const float* __restrict__ lmax) {
    int n = blockIdx.x * blockDim.x + threadIdx.x;
    if (n >= NN) return;
    int d = g_deg[n];
    g_dis[n]  = (d > 0) ? (1.0f / sqrtf((float)d)) : 0.0f;
    g_diag[n] = 2.0f / lmax[g_batch[n]] - 1.0f;
    atomicAdd(&g_cnt[g_batch[n]], 1);   // fused pooling count
}

// multi-block exclusive scan of indeg -> rowptr (3 passes)
__global__ void k_scan1() {
    __shared__ int s[1024];
    int tid = threadIdx.x;
    int i = blockIdx.x * 1024 + tid;
    int v = (i < NN) ? g_indeg[i] : 0;
    int xv = v;
    for (int off = 1; off < 1024; off <<= 1) {
        s[tid] = xv; __syncthreads();
        if (tid >= off) xv += s[tid - off];
        __syncthreads();
    }
    if (i < NN) g_rowptr[i] = xv - v;        // exclusive, pre-offset
    if (tid == 1023) g_bsum[blockIdx.x] = xv;
}
__global__ void k_scan2(int nb) {
    __shared__ int s[64];
    int tid = threadIdx.x;
    int v = (tid < nb) ? g_bsum[tid] : 0;
    int xv = v;
    for (int off = 1; off < 64; off <<= 1) {
        s[tid] = xv; __syncthreads();
        if (tid >= off) xv += s[tid - off];
        __syncthreads();
    }
    g_boff[tid] = xv - v;
}
__global__ void k_scan3() {
    int i = blockIdx.x * 1024 + threadIdx.x;
    if (i < NN) g_rowptr[i] += g_boff[blockIdx.x];
    if (i == 0) g_rowptr[NN] = EE;
}

// fill CSR; edge weight computed inline (k_ew eliminated)
__global__ void k_fill(const float* __restrict__ lmax) {
    int e = blockIdx.x * blockDim.x + threadIdx.x;
    if (e >= EE) return;
    int s = g_src[e], d = g_dstv[e];
    float w = -g_dis[s] * g_dis[d] * (2.0f / lmax[g_batch[s]]);
    int pos = g_rowptr[d] + atomicAdd(&g_cursor[d], 1);
    g_cw[pos] = make_int2(s, __float_as_int(w));
}

// zero K-pad cols [600,640) of both A buffers (after layer-1 192-layout use)
__global__ void k_padzero() {
    int i = blockIdx.x * blockDim.x + threadIdx.x;
    if (i >= NN * 40) return;
    size_t o = (size_t)(i / 40) * LDK_BIG + 600 + (i % 40);
    __nv_bfloat16 z = __float2bfloat16(0.0f);
    g_AH[0][o] = z; g_AL[0][o] = z;
    g_AH[1][o] = z; g_AL[1][o] = z;
}

// ------------------------- sparse propagation (float4 gather, warp/node) ----
// out = alpha*(L_gather + diag*h) + beta*slice0 ; writes bf16 hi/lo (+opt fp32)
template <int F, int LD>
__global__ void k_prop(int sel, int srcS, int dstS, float alpha, float beta,
                       int useSub, int writeF32,
                       __nv_bfloat16* __restrict__ Ah, __nv_bfloat16* __restrict__ Al,
                       int aoff, int lda) {
    int w = (blockIdx.x * blockDim.x + threadIdx.x) >> 5;
    if (w >= NN) return;
    int lane = threadIdx.x & 31;
    float* base = g_T[sel];
    const float* hs  = base + srcS * F;
    float*       out = base + dstS * F;
    const float* sub = base;
    constexpr int NQ = F / 4;             // float4 columns: 50 or 16
    constexpr int NJ = (NQ + 31) / 32;    // 2 or 1
    float4 acc[NJ];
#pragma unroll
    for (int j = 0; j < NJ; j++) acc[j] = make_float4(0.f, 0.f, 0.f, 0.f);

    int e = g_rowptr[w], eend = g_rowptr[w + 1];
#pragma unroll 2
    for (; e < eend; e++) {
        int2 cw = __ldg(&g_cw[e]);
        float we = __int_as_float(cw.y);
        const float4* row = (const float4*)(hs + (size_t)cw.x * LD);
#pragma unroll
        for (int j = 0; j < NJ; j++) {
            int q = lane + 32 * j;
            if (q < NQ) {
                float4 r = __ldg(&row[q]);
                acc[j].x += we * r.x;
                acc[j].y += we * r.y;
                acc[j].z += we * r.z;
                acc[j].w += we * r.w;
            }
        }
    }
    float dg = g_diag[w];
    const float4* hrow = (const float4*)(hs  + (size_t)w * LD);
    float4*       orow = (float4*)      (out + (size_t)w * LD);
    const float4* srow = (const float4*)(sub + (size_t)w * LD);
    size_t abase = (size_t)w * lda + aoff;
#pragma unroll
    for (int j = 0; j < NJ; j++) {
        int q = lane + 32 * j;
        if (q < NQ) {
            float4 h4 = hrow[q];
            float4 v;
            v.x = alpha * (acc[j].x + dg * h4.x);
            v.y = alpha * (acc[j].y + dg * h4.y);
            v.z = alpha * (acc[j].z + dg * h4.z);
            v.w = alpha * (acc[j].w + dg * h4.w);
            if (useSub) {
                float4 s4 = srow[q];
                v.x += beta * s4.x; v.y += beta * s4.y;
                v.z += beta * s4.z; v.w += beta * s4.w;
            }
            if (writeF32) orow[q] = v;
            __nv_bfloat16 h0 = __float2bfloat16(v.x);
            __nv_bfloat16 h1 = __float2bfloat16(v.y);
            __nv_bfloat16 h2 = __float2bfloat16(v.z);
            __nv_bfloat16 h3 = __float2bfloat16(v.w);
            uint2 hp, lp;
            hp.x = (uint32_t)__bfloat16_as_ushort(h0) | ((uint32_t)__bfloat16_as_ushort(h1) << 16);
            hp.y = (uint32_t)__bfloat16_as_ushort(h2) | ((uint32_t)__bfloat16_as_ushort(h3) << 16);
            __nv_bfloat16 l0 = __float2bfloat16(v.x - __bfloat162float(h0));
            __nv_bfloat16 l1 = __float2bfloat16(v.y - __bfloat162float(h1));
            __nv_bfloat16 l2 = __float2bfloat16(v.z - __bfloat162float(h2));
            __nv_bfloat16 l3 = __float2bfloat16(v.w - __bfloat162float(h3));
            lp.x = (uint32_t)__bfloat16_as_ushort(l0) | ((uint32_t)__bfloat16_as_ushort(l1) << 16);
            lp.y = (uint32_t)__bfloat16_as_ushort(l2) | ((uint32_t)__bfloat16_as_ushort(l3) << 16);
            *(uint2*)(Ah + abase + 4 * q) = hp;
            *(uint2*)(Al + abase + 4 * q) = lp;
        }
    }
}

// ------------------------- W -> bf16 hi/lo (transposed, padded 256 x LDK) ---
__global__ void k_cvtB(const float* __restrict__ W, int Kd, int LDK) {
    int k = blockIdx.x * 64 + threadIdx.x;
    int n = blockIdx.y;
    if (k >= LDK) return;
    float v = (n < HH && k < Kd) ? W[(size_t)k * HH + n] : 0.0f;
    __nv_bfloat16 h = __float2bfloat16(v);
    __nv_bfloat16 l = __float2bfloat16(v - __bfloat162float(h));
    size_t o = (size_t)n * LDK + k;
    g_Bh[o] = h;
    g_Bl[o] = l;
}

// ------------------------- HMMA GEMM (mma.sync bf16 3-split, fp32 acc) -----
#define SA_B   144
#define OA_H   0
#define OA_L   18432
#define OB_H   36864
#define OB_L   69120
#define STG    101376
#define SM_TOT (2 * STG)

__device__ __forceinline__ void ldsm_x4(uint32_t addr, uint32_t& r0, uint32_t& r1,
                                        uint32_t& r2, uint32_t& r3) {
    asm volatile("ldmatrix.sync.aligned.m8n8.x4.shared.b16 {%0,%1,%2,%3}, [%4];"
                 : "=r"(r0), "=r"(r1), "=r"(r2), "=r"(r3) : "r"(addr));
}
__device__ __forceinline__ void ldsm_x2(uint32_t addr, uint32_t& r0, uint32_t& r1) {
    asm volatile("ldmatrix.sync.aligned.m8n8.x2.shared.b16 {%0,%1}, [%2];"
                 : "=r"(r0), "=r"(r1) : "r"(addr));
}
__device__ __forceinline__ void mma16816(float* c, const uint32_t* a, const uint32_t* b) {
    asm volatile(
        "mma.sync.aligned.m16n8k16.row.col.f32.bf16.bf16.f32 "
        "{%0,%1,%2,%3}, {%4,%5,%6,%7}, {%8,%9}, {%0,%1,%2,%3};"
        : "+f"(c[0]), "+f"(c[1]), "+f"(c[2]), "+f"(c[3])
        : "r"(a[0]), "r"(a[1]), "r"(a[2]), "r"(a[3]), "r"(b[0]), "r"(b[1]));
}
__device__ __forceinline__ void cp16(uint32_t daddr, const void* saddr, uint32_t srcsz) {
    asm volatile("cp.async.cg.shared.global [%0], [%1], 16, %2;"
                 :: "r"(daddr), "l"(saddr), "r"(srcsz) : "memory");
}

__global__ __launch_bounds__(256, 1) void k_gemm_mma(
        const __nv_bfloat16* __restrict__ Ah, const __nv_bfloat16* __restrict__ Al,
        int LDK, int nch, const float* __restrict__ bias, int selC,
        __nv_bfloat16* __restrict__ nAh, __nv_bfloat16* __restrict__ nAl) {
    extern __shared__ char smdyn[];
    uint32_t sb = smem_to_u32(smdyn);
    int tid = threadIdx.x, lane = tid & 31, wid = tid >> 5;
    int warpM = wid >> 2, warpN = wid & 3;
    int mrow0 = warpM * 64;
    int ncol0 = warpN * 56;
    const int ldk8 = LDK >> 3;
    const int ntiles = (NN + 127) >> 7;   // 391

    const uint4* GAh = (const uint4*)Ah;
    const uint4* GAl = (const uint4*)Al;
    const uint4* GBh = (const uint4*)g_Bh;
    const uint4* GBl = (const uint4*)g_Bl;

    int rr = lane & 7;
    int aRow = rr + 8 * ((lane >> 3) & 1);
    int aK   = 8 * (lane >> 4);
    int bg   = lane >> 3;
    int bRow = rr + 8 * (bg >> 1);
    int bK   = 8 * (bg & 1);
    int bg2  = bg & 1;

    int lrow = tid >> 3, lcc = tid & 7;

    auto issue_stage = [&](int m0, int c, int s) {
        int k8 = c * 8;
        uint32_t sbase = sb + s * STG;
#pragma unroll
        for (int i = 0; i < 4; i++) {
            int row = lrow + 32 * i;
            int gm = m0 + row;
            int ok = (gm < NN);
            size_t gi = (size_t)(ok ? gm : 0) * ldk8 + k8 + lcc;
            uint32_t d = sbase + OA_H + row * SA_B + lcc * 16;
            cp16(d, GAh + gi, ok ? 16u : 0u);
            cp16(d + (OA_L - OA_H), GAl + gi, ok ? 16u : 0u);
        }
#pragma unroll
        for (int i = 0; i < 7; i++) {
            int row = lrow + 32 * i;
            size_t gi = (size_t)row * ldk8 + k8 + lcc;
            uint32_t d = sbase + OB_H + row * SA_B + lcc * 16;
            cp16(d, GBh + gi, 16u);
            cp16(d + (OB_L - OB_H), GBl + gi, 16u);
        }
        asm volatile("cp.async.commit_group;" ::: "memory");
    };

    int p = 0;
    if ((int)blockIdx.x < ntiles) issue_stage(blockIdx.x * 128, 0, 0);

    for (int t = blockIdx.x; t < ntiles; t += gridDim.x) {
        int m0 = t * 128;

        float acc[4][7][4];
#pragma unroll
        for (int i = 0; i < 4; i++)
#pragma unroll
            for (int j = 0; j < 7; j++)
#pragma unroll
                for (int q = 0; q < 4; q++) acc[i][j][q] = 0.0f;

        for (int c = 0; c < nch; c++) {
            asm volatile("cp.async.wait_group 0;" ::: "memory");
            __syncthreads();
            if (c + 1 < nch)
                issue_stage(m0, c + 1, p ^ 1);
            else if (t + (int)gridDim.x < ntiles)
                issue_stage((t + gridDim.x) * 128, 0, p ^ 1);

            uint32_t aH = sb + p * STG + OA_H;
            uint32_t aL = sb + p * STG + OA_L;
            uint32_t bH = sb + p * STG + OB_H;
            uint32_t bL = sb + p * STG + OB_L;

#pragma unroll
            for (int ks = 0; ks < 4; ks++) {
                int kel = ks * 16;
                uint32_t bh[7][2], bl[7][2];
#pragma unroll
                for (int q = 0; q < 3; q++) {
                    uint32_t boff = (uint32_t)((ncol0 + q * 16 + bRow) * SA_B + (kel + bK) * 2);
                    ldsm_x4(bH + boff, bh[2*q][0], bh[2*q][1], bh[2*q+1][0], bh[2*q+1][1]);
                    ldsm_x4(bL + boff, bl[2*q][0], bl[2*q][1], bl[2*q+1][0], bl[2*q+1][1]);
                }
                {
                    uint32_t boff = (uint32_t)((ncol0 + 48 + rr) * SA_B + (kel + 8 * bg2) * 2);
                    ldsm_x2(bH + boff, bh[6][0], bh[6][1]);
                    ldsm_x2(bL + boff, bl[6][0], bl[6][1]);
                }
#pragma unroll
                for (int mt = 0; mt < 4; mt++) {
                    uint32_t aoff = (uint32_t)((mrow0 + mt * 16 + aRow) * SA_B + (kel + aK) * 2);
                    uint32_t ah[4], al[4];
                    ldsm_x4(aH + aoff, ah[0], ah[1], ah[2], ah[3]);
                    ldsm_x4(aL + aoff, al[0], al[1], al[2], al[3]);
#pragma unroll
                    for (int nt = 0; nt < 7; nt++) {
                        mma16816(acc[mt][nt], ah, bh[nt]);
                        mma16816(acc[mt][nt], ah, bl[nt]);
                        mma16816(acc[mt][nt], al, bh[nt]);
                    }
                }
            }
            p ^= 1;
        }

        float* C = g_T[selC];
        int qrow = lane >> 2, qcol = (lane & 3) * 2;
#pragma unroll
        for (int mt = 0; mt < 4; mt++) {
            int row = m0 + mrow0 + mt * 16 + qrow;
#pragma unroll
            for (int nt = 0; nt < 7; nt++) {
                int col = ncol0 + nt * 8 + qcol;
                if (col < HH) {
                    float bz0 = __ldg(&bias[col]);
                    float bz1 = __ldg(&bias[col + 1]);
#pragma unroll
                    for (int half = 0; half < 2; half++) {
                        int r = row + 8 * half;
                        if (r < NN) {
                            float v0 = fmaxf(acc[mt][nt][2 * half]     + bz0, 0.0f);
                            float v1 = fmaxf(acc[mt][nt][2 * half + 1] + bz1, 0.0f);
                            C[(size_t)r * 600 + col]     = v0;
                            C[(size_t)r * 600 + col + 1] = v1;
                            if (nAh) {
                                size_t ab = (size_t)r * LDK_BIG + col;
                                __nv_bfloat16 h0 = __float2bfloat16(v0);
                                __nv_bfloat16 h1 = __float2bfloat16(v1);
                                nAh[ab]     = h0;
                                nAh[ab + 1] = h1;
                                nAl[ab]     = __float2bfloat16(v0 - __bfloat162float(h0));
                                nAl[ab + 1] = __float2bfloat16(v1 - __bfloat162float(h1));
                            }
                        }
                    }
                }
            }
        }
    }
}

// ------------------------- pooling + fc + log_softmax -----------------------
__global__ void k_scan_g() {
    __shared__ int s[GG];
    int tid = threadIdx.x;
    int v = g_cnt[tid];
    int xv = v;
    for (int off = 1; off < GG; off <<= 1) {
        s[tid] = xv; __syncthreads();
        if (tid >= off) xv += s[tid - off];
        __syncthreads();
    }
    g_gstart[tid] = xv - v;
    if (tid == GG - 1) g_gstart[GG] = xv;
}

// block per graph: 4 row-groups x 64 float4-cols, smem combine
__global__ void k_pool() {
    __shared__ float4 ssum[4][52], smax[4][52];
    int g = blockIdx.x;
    int q = threadIdx.x & 63, rg = threadIdx.x >> 6;
    int s = g_gstart[g], e = g_gstart[g + 1];
    float4 sum = make_float4(0.f, 0.f, 0.f, 0.f);
    float4 mx  = make_float4(-3.4e38f, -3.4e38f, -3.4e38f, -3.4e38f);
    if (q < 50) {
        for (int n = s + rg; n < e; n += 4) {
            const float4* row = (const float4*)(g_T[0] + (size_t)n * 600);
            float4 v = __ldg(&row[q]);
            sum.x += v.x; sum.y += v.y; sum.z += v.z; sum.w += v.w;
            mx.x = fmaxf(mx.x, v.x); mx.y = fmaxf(mx.y, v.y);
            mx.z = fmaxf(mx.z, v.z); mx.w = fmaxf(mx.w, v.w);
        }
        ssum[rg][q] = sum; smax[rg][q] = mx;
    }
    __syncthreads();
    if (rg == 0 && q < 50) {
#pragma unroll
        for (int r = 1; r < 4; r++) {
            float4 a = ssum[r][q], b = smax[r][q];
            sum.x += a.x; sum.y += a.y; sum.z += a.z; sum.w += a.w;
            mx.x = fmaxf(mx.x, b.x); mx.y = fmaxf(mx.y, b.y);
            mx.z = fmaxf(mx.z, b.z); mx.w = fmaxf(mx.w, b.w);
        }
        float c = fmaxf((float)(e - s), 1.0f);
        float* pm = &g_pool[g * 400 + 4 * q];
        pm[0] = sum.x / c; pm[1] = sum.y / c; pm[2] = sum.z / c; pm[3] = sum.w / c;
        float* px = &g_pool[g * 400 + HH + 4 * q];
        px[0] = mx.x; px[1] = mx.y; px[2] = mx.z; px[3] = mx.w;
    }
}

__global__ void k_fc(const float* __restrict__ fw, const float* __restrict__ fb,
                     float* __restrict__ out) {
    int g = blockIdx.x * blockDim.x + threadIdx.x;
    if (g >= GG) return;
    float z0 = fb[0], z1 = fb[1];
    const float* p = &g_pool[g * 400];
    for (int j = 0; j < 400; j++) {
        float v = p[j];
        z0 += v * fw[2 * j];
        z1 += v * fw[2 * j + 1];
    }
    float m = fmaxf(z0, z1);
    float l = m + logf(expf(z0 - m) + expf(z1 - m));
    out[2 * g]     = z0 - l;
    out[2 * g + 1] = z1 - l;
}

// ------------------------- launch ------------------------------------------
extern "C" void kernel_launch(void* const* d_in, const int* in_sizes, int n_in,
                              void* d_out, int out_size) {
    const float* x     = (const float*)d_in[0];
    const void*  ei    = d_in[1];
    const void*  batch = d_in[2];
    const float* lmax  = (const float*)d_in[3];
    const float* W1 = (const float*)d_in[4];  const float* b1 = (const float*)d_in[5];
    const float* W2 = (const float*)d_in[6];  const float* b2 = (const float*)d_in[7];
    const float* W3 = (const float*)d_in[8];  const float* b3 = (const float*)d_in[9];
    const float* W4 = (const float*)d_in[10]; const float* b4 = (const float*)d_in[11];
    const float* fw = (const float*)d_in[12]; const float* fb = (const float*)d_in[13];
    float* out = (float*)d_out;

    cudaFuncSetAttribute(k_gemm_mma, cudaFuncAttributeMaxDynamicSharedMemorySize, SM_TOT);

    const int TB = 256;
    int nbN = (NN + TB - 1) / TB;
    int nbE = (EE + TB - 1) / TB;
    int nbS = (NN + 1023) / 1024;

    __nv_bfloat16 *AH0, *AL0, *AH1, *AL1;
    cudaGetSymbolAddress((void**)&AH0, g_AH);  AH1 = AH0 + (size_t)NN * LDK_BIG;
    cudaGetSymbolAddress((void**)&AL0, g_AL);  AL1 = AL0 + (size_t)NN * LDK_BIG;

    k_init<<<nbN, TB>>>(ei);
    k_cvt_all<<<nbE, TB>>>(ei, batch, x);
    k_node<<<nbN, TB>>>(lmax);
    k_scan1<<<nbS, 1024>>>();
    k_scan2<<<1, 64>>>(nbS);
    k_scan3<<<nbS, 1024>>>();
    k_fill<<<nbE, TB>>>(lmax);

    int propBlocks = (NN * 32 + TB - 1) / TB;
    dim3 cvtSB((LDK_S + 63) / 64, 256), cvtBB((LDK_BIG + 63) / 64, 256);

    // layer 1
    k_prop<64, 192><<<propBlocks, TB>>>(0, 0, 1, 1.0f, 0.0f, 0, 1, AH0, AL0, 64, LDK_S);
    k_prop<64, 192><<<propBlocks, TB>>>(0, 1, 2, 2.0f, -1.0f, 1, 0, AH0, AL0, 128, LDK_S);
    k_cvtB<<<cvtSB, 64>>>(W1, 192, LDK_S);
    k_gemm_mma<<<GEMM_GRID, 256, SM_TOT>>>(AH0, AL0, LDK_S, 3, b1, 1, AH1, AL1);
    k_padzero<<<(NN * 40 + TB - 1) / TB, TB>>>();

    // layer 2
    k_prop<200, 600><<<propBlocks, TB>>>(1, 0, 1, 1.0f, 0.0f, 0, 1, AH1, AL1, 200, LDK_BIG);
    k_prop<200, 600><<<propBlocks, TB>>>(1, 1, 2, 2.0f, -1.0f, 1, 0, AH1, AL1, 400, LDK_BIG);
    k_cvtB<<<cvtBB, 64>>>(W2, 600, LDK_BIG);
    k_gemm_mma<<<GEMM_GRID, 256, SM_TOT>>>(AH1, AL1, LDK_BIG, 10, b2, 0, AH0, AL0);

    // layer 3
    k_prop<200, 600><<<propBlocks, TB>>>(0, 0, 1, 1.0f, 0.0f, 0, 1, AH0, AL0, 200, LDK_BIG);
    k_prop<200, 600><<<propBlocks, TB>>>(0, 1, 2, 2.0f, -1.0f, 1, 0, AH0, AL0, 400, LDK_BIG);
    k_cvtB<<<cvtBB, 64>>>(W3, 600, LDK_BIG);
    k_gemm_mma<<<GEMM_GRID, 256, SM_TOT>>>(AH0, AL0, LDK_BIG, 10, b3, 1, AH1, AL1);

    // layer 4
    k_prop<200, 600><<<propBlocks, TB>>>(1, 0, 1, 1.0f, 0.0f, 0, 1, AH1, AL1, 200, LDK_BIG);
    k_prop<200, 600><<<propBlocks, TB>>>(1, 1, 2, 2.0f, -1.0f, 1, 0, AH1, AL1, 400, LDK_BIG);
    k_cvtB<<<cvtBB, 64>>>(W4, 600, LDK_BIG);
    k_gemm_mma<<<GEMM_GRID, 256, SM_TOT>>>(AH1, AL1, LDK_BIG, 10, b4, 0, nullptr, nullptr);

    // pooling + fc + log_softmax
    k_scan_g<<<1, GG>>>();
    k_pool<<<GG, TB>>>();
    k_fc<<<1, GG>>>(fw, fb, out);
}

// round 13
// speedup vs baseline: 2.0879x; 1.1112x over previous
#include <cuda_runtime.h>
#include <cuda_bf16.h>
#include <math.h>
#include <stdint.h>

#define NN  50000
#define EE  800000
#define FIN 64
#define HH  200
#define GG  256

#define LDK_BIG 640   // 3*200 padded to /64
#define LDK_S   192   // 3*64
#define GEMM_GRID 152 // persistent CTAs (GB300: 152 SMs)

// ------------------------- scratch (device globals; no allocation) ---------
__device__ __align__(256) float g_T[2][(size_t)NN * 600];   // ping-pong fp32 [N][3F]
__device__ __align__(256) __nv_bfloat16 g_AH[2][(size_t)NN * LDK_BIG];
__device__ __align__(256) __nv_bfloat16 g_AL[2][(size_t)NN * LDK_BIG];
__device__ __align__(256) __nv_bfloat16 g_Bh[256 * LDK_BIG];
__device__ __align__(256) __nv_bfloat16 g_Bl[256 * LDK_BIG];
__device__ int   g_src[EE], g_dstv[EE];
__device__ int2  g_cw[EE];                 // packed (col, weight-bits) CSR payload
__device__ int   g_deg[NN], g_indeg[NN], g_cursor[NN], g_batch[NN];
__device__ float g_dis[NN], g_diag[NN];
__device__ int   g_rowptr[NN + 1];
__device__ int   g_bsum[64], g_boff[64];
__device__ float g_pool[GG * 400];
__device__ int   g_is64;

__device__ __forceinline__ uint32_t smem_to_u32(const void* p) {
    uint32_t a;
    asm("{ .reg .u64 t; cvta.to.shared.u64 t, %1; cvt.u32.u64 %0, t; }" : "=r"(a) : "l"(p));
    return a;
}

// ------------------------- init: zero counters + dtype detect ---------------
__global__ void k_init(const void* ei) {
    int i = blockIdx.x * blockDim.x + threadIdx.x;
    if (i < NN) { g_deg[i] = 0; g_indeg[i] = 0; g_cursor[i] = 0; }
    if (i == 0) {
        const unsigned* u = (const unsigned*)ei;
        int z = 0;
        for (int j = 0; j < 32; j++)
            if (u[2 * j + 1] == 0u) z++;
        g_is64 = (z >= 16) ? 1 : 0;   // int64 little-endian: high words all zero
    }
}

// ---------- fused: edge/batch convert + degree atomics + x copy -------------
__global__ void k_cvt_all(const void* ei, const void* b, const float* __restrict__ x) {
    int stride = gridDim.x * blockDim.x;
    int t0 = blockIdx.x * blockDim.x + threadIdx.x;
    int is64 = g_is64;
    if (is64) {
        const long long* p = (const long long*)ei;
        for (int e = t0; e < EE; e += stride) {
            int s = (int)p[e], d = (int)p[EE + e];
            g_src[e] = s; g_dstv[e] = d;
            atomicAdd(&g_deg[s], 1);
            atomicAdd(&g_indeg[d], 1);
        }
        const long long* pb = (const long long*)b;
        for (int n = t0; n < NN; n += stride) g_batch[n] = (int)pb[n];
    } else {
        const int* p = (const int*)ei;
        for (int e = t0; e < EE; e += stride) {
            int s = p[e], d = p[EE + e];
            g_src[e] = s; g_dstv[e] = d;
            atomicAdd(&g_deg[s], 1);
            atomicAdd(&g_indeg[d], 1);
        }
        const int* pb = (const int*)b;
        for (int n = t0; n < NN; n += stride) g_batch[n] = pb[n];
    }
    for (int i = t0; i < NN * FIN; i += stride) {
        int n = i >> 6, f = i & 63;
        float v = x[i];
        g_T[0][(size_t)n * 192 + f] = v;
        __nv_bfloat16 h = __float2bfloat16(v);
        size_t o = (size_t)n * LDK_S + f;
        g_AH[0][o] = h;
        g_AL[0][o] = __float2bfloat16(v - __bfloat162float(h));
    }
}

__global__ void k_node(const float* __restrict__ lmax) {
    int n = blockIdx.x * blockDim.x + threadIdx.x;
    if (n >= NN) return;
    int d = g_deg[n];
    g_dis[n]  = (d > 0) ? (1.0f / sqrtf((float)d)) : 0.0f;
    g_diag[n] = 2.0f / lmax[g_batch[n]] - 1.0f;
}

// multi-block exclusive scan of indeg -> rowptr (3 passes)
__global__ void k_scan1() {
    __shared__ int s[1024];
    int tid = threadIdx.x;
    int i = blockIdx.x * 1024 + tid;
    int v = (i < NN) ? g_indeg[i] : 0;
    int xv = v;
    for (int off = 1; off < 1024; off <<= 1) {
        s[tid] = xv; __syncthreads();
        if (tid >= off) xv += s[tid - off];
        __syncthreads();
    }
    if (i < NN) g_rowptr[i] = xv - v;        // exclusive, pre-offset
    if (tid == 1023) g_bsum[blockIdx.x] = xv;
}
__global__ void k_scan2(int nb) {
    __shared__ int s[64];
    int tid = threadIdx.x;
    int v = (tid < nb) ? g_bsum[tid] : 0;
    int xv = v;
    for (int off = 1; off < 64; off <<= 1) {
        s[tid] = xv; __syncthreads();
        if (tid >= off) xv += s[tid - off];
        __syncthreads();
    }
    g_boff[tid] = xv - v;
}
__global__ void k_scan3() {
    int i = blockIdx.x * 1024 + threadIdx.x;
    if (i < NN) g_rowptr[i] += g_boff[blockIdx.x];
    if (i == 0) g_rowptr[NN] = EE;
}

// fill CSR; edge weight computed inline
__global__ void k_fill(const float* __restrict__ lmax) {
    int e = blockIdx.x * blockDim.x + threadIdx.x;
    if (e >= EE) return;
    int s = g_src[e], d = g_dstv[e];
    float w = -g_dis[s] * g_dis[d] * (2.0f / lmax[g_batch[s]]);
    int pos = g_rowptr[d] + atomicAdd(&g_cursor[d], 1);
    g_cw[pos] = make_int2(s, __float_as_int(w));
}

// zero K-pad cols [600,640) of both A buffers.
// MUST run after the layer-1 GEMM: during layer 1 the A buffers hold LDK_S=192
// layout data whose linear range overlaps these pad offsets.
__global__ void k_padzero() {
    int i = blockIdx.x * blockDim.x + threadIdx.x;
    if (i >= NN * 40) return;
    size_t o = (size_t)(i / 40) * LDK_BIG + 600 + (i % 40);
    __nv_bfloat16 z = __float2bfloat16(0.0f);
    g_AH[0][o] = z; g_AL[0][o] = z;
    g_AH[1][o] = z; g_AL[1][o] = z;
}

// ------------------------- sparse propagation (float4 gather, warp/node) ----
// out = alpha*(L_gather + diag*h) + beta*slice0 ; writes bf16 hi/lo (+opt fp32)
template <int F, int LD>
__global__ void k_prop(int sel, int srcS, int dstS, float alpha, float beta,
                       int useSub, int writeF32,
                       __nv_bfloat16* __restrict__ Ah, __nv_bfloat16* __restrict__ Al,
                       int aoff, int lda) {
    int w = (blockIdx.x * blockDim.x + threadIdx.x) >> 5;
    if (w >= NN) return;
    int lane = threadIdx.x & 31;
    float* base = g_T[sel];
    const float* hs  = base + srcS * F;
    float*       out = base + dstS * F;
    const float* sub = base;
    constexpr int NQ = F / 4;             // float4 columns: 50 or 16
    constexpr int NJ = (NQ + 31) / 32;    // 2 or 1
    float4 acc[NJ];
#pragma unroll
    for (int j = 0; j < NJ; j++) acc[j] = make_float4(0.f, 0.f, 0.f, 0.f);

    int e = g_rowptr[w], eend = g_rowptr[w + 1];
#pragma unroll 4
    for (; e < eend; e++) {
        int2 cw = __ldg(&g_cw[e]);
        float we = __int_as_float(cw.y);
        const float4* row = (const float4*)(hs + (size_t)cw.x * LD);
#pragma unroll
        for (int j = 0; j < NJ; j++) {
            int q = lane + 32 * j;
            if (q < NQ) {
                float4 r = __ldg(&row[q]);
                acc[j].x += we * r.x;
                acc[j].y += we * r.y;
                acc[j].z += we * r.z;
                acc[j].w += we * r.w;
            }
        }
    }
    float dg = g_diag[w];
    const float4* hrow = (const float4*)(hs  + (size_t)w * LD);
    float4*       orow = (float4*)      (out + (size_t)w * LD);
    const float4* srow = (const float4*)(sub + (size_t)w * LD);
    size_t abase = (size_t)w * lda + aoff;
#pragma unroll
    for (int j = 0; j < NJ; j++) {
        int q = lane + 32 * j;
        if (q < NQ) {
            float4 h4 = hrow[q];
            float4 v;
            v.x = alpha * (acc[j].x + dg * h4.x);
            v.y = alpha * (acc[j].y + dg * h4.y);
            v.z = alpha * (acc[j].z + dg * h4.z);
            v.w = alpha * (acc[j].w + dg * h4.w);
            if (useSub) {
                float4 s4 = srow[q];
                v.x += beta * s4.x; v.y += beta * s4.y;
                v.z += beta * s4.z; v.w += beta * s4.w;
            }
            if (writeF32) orow[q] = v;
            __nv_bfloat16 h0 = __float2bfloat16(v.x);
            __nv_bfloat16 h1 = __float2bfloat16(v.y);
            __nv_bfloat16 h2 = __float2bfloat16(v.z);
            __nv_bfloat16 h3 = __float2bfloat16(v.w);
            uint2 hp, lp;
            hp.x = (uint32_t)__bfloat16_as_ushort(h0) | ((uint32_t)__bfloat16_as_ushort(h1) << 16);
            hp.y = (uint32_t)__bfloat16_as_ushort(h2) | ((uint32_t)__bfloat16_as_ushort(h3) << 16);
            __nv_bfloat16 l0 = __float2bfloat16(v.x - __bfloat162float(h0));
            __nv_bfloat16 l1 = __float2bfloat16(v.y - __bfloat162float(h1));
            __nv_bfloat16 l2 = __float2bfloat16(v.z - __bfloat162float(h2));
            __nv_bfloat16 l3 = __float2bfloat16(v.w - __bfloat162float(h3));
            lp.x = (uint32_t)__bfloat16_as_ushort(l0) | ((uint32_t)__bfloat16_as_ushort(l1) << 16);
            lp.y = (uint32_t)__bfloat16_as_ushort(l2) | ((uint32_t)__bfloat16_as_ushort(l3) << 16);
            *(uint2*)(Ah + abase + 4 * q) = hp;
            *(uint2*)(Al + abase + 4 * q) = lp;
        }
    }
}

// ------------------------- W -> bf16 hi/lo (transposed, padded 256 x LDK) ---
__global__ void k_cvtB(const float* __restrict__ W, int Kd, int LDK) {
    int k = blockIdx.x * 64 + threadIdx.x;
    int n = blockIdx.y;
    if (k >= LDK) return;
    float v = (n < HH && k < Kd) ? W[(size_t)k * HH + n] : 0.0f;
    __nv_bfloat16 h = __float2bfloat16(v);
    __nv_bfloat16 l = __float2bfloat16(v - __bfloat162float(h));
    size_t o = (size_t)n * LDK + k;
    g_Bh[o] = h;
    g_Bl[o] = l;
}

// ------------------------- HMMA GEMM (mma.sync bf16 3-split, fp32 acc) -----
#define SA_B   144
#define OA_H   0
#define OA_L   18432
#define OB_H   36864
#define OB_L   69120
#define STG    101376
#define SM_TOT (2 * STG)

__device__ __forceinline__ void ldsm_x4(uint32_t addr, uint32_t& r0, uint32_t& r1,
                                        uint32_t& r2, uint32_t& r3) {
    asm volatile("ldmatrix.sync.aligned.m8n8.x4.shared.b16 {%0,%1,%2,%3}, [%4];"
                 : "=r"(r0), "=r"(r1), "=r"(r2), "=r"(r3) : "r"(addr));
}
__device__ __forceinline__ void ldsm_x2(uint32_t addr, uint32_t& r0, uint32_t& r1) {
    asm volatile("ldmatrix.sync.aligned.m8n8.x2.shared.b16 {%0,%1}, [%2];"
                 : "=r"(r0), "=r"(r1) : "r"(addr));
}
__device__ __forceinline__ void mma16816(float* c, const uint32_t* a, const uint32_t* b) {
    asm volatile(
        "mma.sync.aligned.m16n8k16.row.col.f32.bf16.bf16.f32 "
        "{%0,%1,%2,%3}, {%4,%5,%6,%7}, {%8,%9}, {%0,%1,%2,%3};"
        : "+f"(c[0]), "+f"(c[1]), "+f"(c[2]), "+f"(c[3])
        : "r"(a[0]), "r"(a[1]), "r"(a[2]), "r"(a[3]), "r"(b[0]), "r"(b[1]));
}
__device__ __forceinline__ void cp16(uint32_t daddr, const void* saddr, uint32_t srcsz) {
    asm volatile("cp.async.cg.shared.global [%0], [%1], 16, %2;"
                 :: "r"(daddr), "l"(saddr), "r"(srcsz) : "memory");
}

__global__ __launch_bounds__(256, 1) void k_gemm_mma(
        const __nv_bfloat16* __restrict__ Ah, const __nv_bfloat16* __restrict__ Al,
        int LDK, int nch, const float* __restrict__ bias, int selC,
        __nv_bfloat16* __restrict__ nAh, __nv_bfloat16* __restrict__ nAl) {
    extern __shared__ char smdyn[];
    uint32_t sb = smem_to_u32(smdyn);
    int tid = threadIdx.x, lane = tid & 31, wid = tid >> 5;
    int warpM = wid >> 2, warpN = wid & 3;
    int mrow0 = warpM * 64;
    int ncol0 = warpN * 56;
    const int ldk8 = LDK >> 3;
    const int ntiles = (NN + 127) >> 7;   // 391

    const uint4* GAh = (const uint4*)Ah;
    const uint4* GAl = (const uint4*)Al;
    const uint4* GBh = (const uint4*)g_Bh;
    const uint4* GBl = (const uint4*)g_Bl;

    int rr = lane & 7;
    int aRow = rr + 8 * ((lane >> 3) & 1);
    int aK   = 8 * (lane >> 4);
    int bg   = lane >> 3;
    int bRow = rr + 8 * (bg >> 1);
    int bK   = 8 * (bg & 1);
    int bg2  = bg & 1;

    int lrow = tid >> 3, lcc = tid & 7;

    auto issue_stage = [&](int m0, int c, int s) {
        int k8 = c * 8;
        uint32_t sbase = sb + s * STG;
#pragma unroll
        for (int i = 0; i < 4; i++) {
            int row = lrow + 32 * i;
            int gm = m0 + row;
            int ok = (gm < NN);
            size_t gi = (size_t)(ok ? gm : 0) * ldk8 + k8 + lcc;
            uint32_t d = sbase + OA_H + row * SA_B + lcc * 16;
            cp16(d, GAh + gi, ok ? 16u : 0u);
            cp16(d + (OA_L - OA_H), GAl + gi, ok ? 16u : 0u);
        }
#pragma unroll
        for (int i = 0; i < 7; i++) {
            int row = lrow + 32 * i;
            size_t gi = (size_t)row * ldk8 + k8 + lcc;
            uint32_t d = sbase + OB_H + row * SA_B + lcc * 16;
            cp16(d, GBh + gi, 16u);
            cp16(d + (OB_L - OB_H), GBl + gi, 16u);
        }
        asm volatile("cp.async.commit_group;" ::: "memory");
    };

    int p = 0;
    if ((int)blockIdx.x < ntiles) issue_stage(blockIdx.x * 128, 0, 0);

    for (int t = blockIdx.x; t < ntiles; t += gridDim.x) {
        int m0 = t * 128;

        float acc[4][7][4];
#pragma unroll
        for (int i = 0; i < 4; i++)
#pragma unroll
            for (int j = 0; j < 7; j++)
#pragma unroll
                for (int q = 0; q < 4; q++) acc[i][j][q] = 0.0f;

        for (int c = 0; c < nch; c++) {
            asm volatile("cp.async.wait_group 0;" ::: "memory");
            __syncthreads();
            if (c + 1 < nch)
                issue_stage(m0, c + 1, p ^ 1);
            else if (t + (int)gridDim.x < ntiles)
                issue_stage((t + gridDim.x) * 128, 0, p ^ 1);

            uint32_t aH = sb + p * STG + OA_H;
            uint32_t aL = sb + p * STG + OA_L;
            uint32_t bH = sb + p * STG + OB_H;
            uint32_t bL = sb + p * STG + OB_L;

#pragma unroll
            for (int ks = 0; ks < 4; ks++) {
                int kel = ks * 16;
                uint32_t bh[7][2], bl[7][2];
#pragma unroll
                for (int q = 0; q < 3; q++) {
                    uint32_t boff = (uint32_t)((ncol0 + q * 16 + bRow) * SA_B + (kel + bK) * 2);
                    ldsm_x4(bH + boff, bh[2*q][0], bh[2*q][1], bh[2*q+1][0], bh[2*q+1][1]);
                    ldsm_x4(bL + boff, bl[2*q][0], bl[2*q][1], bl[2*q+1][0], bl[2*q+1][1]);
                }
                {
                    uint32_t boff = (uint32_t)((ncol0 + 48 + rr) * SA_B + (kel + 8 * bg2) * 2);
                    ldsm_x2(bH + boff, bh[6][0], bh[6][1]);
                    ldsm_x2(bL + boff, bl[6][0], bl[6][1]);
                }
#pragma unroll
                for (int mt = 0; mt < 4; mt++) {
                    uint32_t aoff = (uint32_t)((mrow0 + mt * 16 + aRow) * SA_B + (kel + aK) * 2);
                    uint32_t ah[4], al[4];
                    ldsm_x4(aH + aoff, ah[0], ah[1], ah[2], ah[3]);
                    ldsm_x4(aL + aoff, al[0], al[1], al[2], al[3]);
#pragma unroll
                    for (int nt = 0; nt < 7; nt++) {
                        mma16816(acc[mt][nt], ah, bh[nt]);
                        mma16816(acc[mt][nt], ah, bl[nt]);
                        mma16816(acc[mt][nt], al, bh[nt]);
                    }
                }
            }
            p ^= 1;
        }

        // epilogue: bias + relu; vectorized stores
        float* C = g_T[selC];
        int qrow = lane >> 2, qcol = (lane & 3) * 2;
#pragma unroll
        for (int mt = 0; mt < 4; mt++) {
            int row = m0 + mrow0 + mt * 16 + qrow;
#pragma unroll
            for (int nt = 0; nt < 7; nt++) {
                int col = ncol0 + nt * 8 + qcol;
                if (col < HH) {
                    float bz0 = __ldg(&bias[col]);
                    float bz1 = __ldg(&bias[col + 1]);
#pragma unroll
                    for (int half = 0; half < 2; half++) {
                        int r = row + 8 * half;
                        if (r < NN) {
                            float v0 = fmaxf(acc[mt][nt][2 * half]     + bz0, 0.0f);
                            float v1 = fmaxf(acc[mt][nt][2 * half + 1] + bz1, 0.0f);
                            *(float2*)(C + (size_t)r * 600 + col) = make_float2(v0, v1);
                            if (nAh) {
                                size_t ab = (size_t)r * LDK_BIG + col;
                                __nv_bfloat16 h0 = __float2bfloat16(v0);
                                __nv_bfloat16 h1 = __float2bfloat16(v1);
                                uint32_t hp = (uint32_t)__bfloat16_as_ushort(h0) |
                                              ((uint32_t)__bfloat16_as_ushort(h1) << 16);
                                __nv_bfloat16 l0 = __float2bfloat16(v0 - __bfloat162float(h0));
                                __nv_bfloat16 l1 = __float2bfloat16(v1 - __bfloat162float(h1));
                                uint32_t lp = (uint32_t)__bfloat16_as_ushort(l0) |
                                              ((uint32_t)__bfloat16_as_ushort(l1) << 16);
                                *(uint32_t*)(nAh + ab) = hp;
                                *(uint32_t*)(nAl + ab) = lp;
                            }
                        }
                    }
                }
            }
        }
    }
}

// ------------------------- pooling (binary search over sorted batch) --------
__global__ void k_pool() {
    __shared__ float4 ssum[4][52], smax[4][52];
    int g = blockIdx.x;
    int q = threadIdx.x & 63, rg = threadIdx.x >> 6;
    // segment bounds via binary search (batch sorted ascending)
    int lo = 0, hi = NN;
    while (lo < hi) { int m = (lo + hi) >> 1; if (g_batch[m] < g) lo = m + 1; else hi = m; }
    int s = lo;
    lo = 0; hi = NN;
    while (lo < hi) { int m = (lo + hi) >> 1; if (g_batch[m] < g + 1) lo = m + 1; else hi = m; }
    int e = lo;

    float4 sum = make_float4(0.f, 0.f, 0.f, 0.f);
    float4 mx  = make_float4(-3.4e38f, -3.4e38f, -3.4e38f, -3.4e38f);
    if (q < 50) {
        for (int n = s + rg; n < e; n += 4) {
            const float4* row = (const float4*)(g_T[0] + (size_t)n * 600);
            float4 v = __ldg(&row[q]);
            sum.x += v.x; sum.y += v.y; sum.z += v.z; sum.w += v.w;
            mx.x = fmaxf(mx.x, v.x); mx.y = fmaxf(mx.y, v.y);
            mx.z = fmaxf(mx.z, v.z); mx.w = fmaxf(mx.w, v.w);
        }
        ssum[rg][q] = sum; smax[rg][q] = mx;
    }
    __syncthreads();
    if (rg == 0 && q < 50) {
#pragma unroll
        for (int r = 1; r < 4; r++) {
            float4 a = ssum[r][q], b = smax[r][q];
            sum.x += a.x; sum.y += a.y; sum.z += a.z; sum.w += a.w;
            mx.x = fmaxf(mx.x, b.x); mx.y = fmaxf(mx.y, b.y);
            mx.z = fmaxf(mx.z, b.z); mx.w = fmaxf(mx.w, b.w);
        }
        float c = fmaxf((float)(e - s), 1.0f);
        float* pm = &g_pool[g * 400 + 4 * q];
        pm[0] = sum.x / c; pm[1] = sum.y / c; pm[2] = sum.z / c; pm[3] = sum.w / c;
        float* px = &g_pool[g * 400 + HH + 4 * q];
        px[0] = mx.x; px[1] = mx.y; px[2] = mx.z; px[3] = mx.w;
    }
}

// warp per graph; shuffle reduction
__global__ void k_fc(const float* __restrict__ fw, const float* __restrict__ fb,
                     float* __restrict__ out) {
    int wid = threadIdx.x >> 5, lane = threadIdx.x & 31;
    int g = blockIdx.x * 8 + wid;
    if (g >= GG) return;
    float z0 = 0.0f, z1 = 0.0f;
    const float* p = &g_pool[g * 400];
    for (int j = lane; j < 400; j += 32) {
        float v = p[j];
        z0 += v * __ldg(&fw[2 * j]);
        z1 += v * __ldg(&fw[2 * j + 1]);
    }
#pragma unroll
    for (int off = 16; off > 0; off >>= 1) {
        z0 += __shfl_xor_sync(0xFFFFFFFF, z0, off);
        z1 += __shfl_xor_sync(0xFFFFFFFF, z1, off);
    }
    if (lane == 0) {
        z0 += fb[0]; z1 += fb[1];
        float m = fmaxf(z0, z1);
        float l = m + logf(expf(z0 - m) + expf(z1 - m));
        out[2 * g]     = z0 - l;
        out[2 * g + 1] = z1 - l;
    }
}

// ------------------------- launch ------------------------------------------
extern "C" void kernel_launch(void* const* d_in, const int* in_sizes, int n_in,
                              void* d_out, int out_size) {
    const float* x     = (const float*)d_in[0];
    const void*  ei    = d_in[1];
    const void*  batch = d_in[2];
    const float* lmax  = (const float*)d_in[3];
    const float* W1 = (const float*)d_in[4];  const float* b1 = (const float*)d_in[5];
    const float* W2 = (const float*)d_in[6];  const float* b2 = (const float*)d_in[7];
    const float* W3 = (const float*)d_in[8];  const float* b3 = (const float*)d_in[9];
    const float* W4 = (const float*)d_in[10]; const float* b4 = (const float*)d_in[11];
    const float* fw = (const float*)d_in[12]; const float* fb = (const float*)d_in[13];
    float* out = (float*)d_out;

    cudaFuncSetAttribute(k_gemm_mma, cudaFuncAttributeMaxDynamicSharedMemorySize, SM_TOT);

    const int TB = 256;
    int nbN = (NN + TB - 1) / TB;
    int nbE = (EE + TB - 1) / TB;
    int nbS = (NN + 1023) / 1024;

    __nv_bfloat16 *AH0, *AL0, *AH1, *AL1;
    cudaGetSymbolAddress((void**)&AH0, g_AH);  AH1 = AH0 + (size_t)NN * LDK_BIG;
    cudaGetSymbolAddress((void**)&AL0, g_AL);  AL1 = AL0 + (size_t)NN * LDK_BIG;

    k_init<<<nbN, TB>>>(ei);
    k_cvt_all<<<nbE, TB>>>(ei, batch, x);
    k_node<<<nbN, TB>>>(lmax);
    k_scan1<<<nbS, 1024>>>();
    k_scan2<<<1, 64>>>(nbS);
    k_scan3<<<nbS, 1024>>>();
    k_fill<<<nbE, TB>>>(lmax);

    int propBlocks = (NN * 32 + TB - 1) / TB;
    dim3 cvtSB((LDK_S + 63) / 64, 256), cvtBB((LDK_BIG + 63) / 64, 256);

    // layer 1 (A buffers in LDK_S layout until the GEMM below consumes them)
    k_prop<64, 192><<<propBlocks, TB>>>(0, 0, 1, 1.0f, 0.0f, 0, 1, AH0, AL0, 64, LDK_S);
    k_prop<64, 192><<<propBlocks, TB>>>(0, 1, 2, 2.0f, -1.0f, 1, 0, AH0, AL0, 128, LDK_S);
    k_cvtB<<<cvtSB, 64>>>(W1, 192, LDK_S);
    k_gemm_mma<<<GEMM_GRID, 256, SM_TOT>>>(AH0, AL0, LDK_S, 3, b1, 1, AH1, AL1);
    k_padzero<<<(NN * 40 + TB - 1) / TB, TB>>>();   // AFTER layer-1 GEMM (layout switch)

    // layer 2
    k_prop<200, 600><<<propBlocks, TB>>>(1, 0, 1, 1.0f, 0.0f, 0, 1, AH1, AL1, 200, LDK_BIG);
    k_prop<200, 600><<<propBlocks, TB>>>(1, 1, 2, 2.0f, -1.0f, 1, 0, AH1, AL1, 400, LDK_BIG);
    k_cvtB<<<cvtBB, 64>>>(W2, 600, LDK_BIG);
    k_gemm_mma<<<GEMM_GRID, 256, SM_TOT>>>(AH1, AL1, LDK_BIG, 10, b2, 0, AH0, AL0);

    // layer 3
    k_prop<200, 600><<<propBlocks, TB>>>(0, 0, 1, 1.0f, 0.0f, 0, 1, AH0, AL0, 200, LDK_BIG);
    k_prop<200, 600><<<propBlocks, TB>>>(0, 1, 2, 2.0f, -1.0f, 1, 0, AH0, AL0, 400, LDK_BIG);
    k_cvtB<<<cvtBB, 64>>>(W3, 600, LDK_BIG);
    k_gemm_mma<<<GEMM_GRID, 256, SM_TOT>>>(AH0, AL0, LDK_BIG, 10, b3, 1, AH1, AL1);

    // layer 4
    k_prop<200, 600><<<propBlocks, TB>>>(1, 0, 1, 1.0f, 0.0f, 0, 1, AH1, AL1, 200, LDK_BIG);
    k_prop<200, 600><<<propBlocks, TB>>>(1, 1, 2, 2.0f, -1.0f, 1, 0, AH1, AL1, 400, LDK_BIG);
    k_cvtB<<<cvtBB, 64>>>(W4, 600, LDK_BIG);
    k_gemm_mma<<<GEMM_GRID, 256, SM_TOT>>>(AH1, AL1, LDK_BIG, 10, b4, 0, nullptr, nullptr);

    // pooling + fc + log_softmax
    k_pool<<<GG, TB>>>();
    k_fc<<<GG / 8, TB>>>(fw, fb, out);
}

// round 14
// speedup vs baseline: 2.2292x; 1.0677x over previous
#include <cuda_runtime.h>
#include <cuda_bf16.h>
#include <math.h>
#include <stdint.h>

#define NN  50000
#define EE  800000
#define FIN 64
#define HH  200
#define GG  256

#define LDK_BIG 640   // 3*200 padded to /64
#define LDK_S   192   // 3*64
#define GEMM_GRID 152 // persistent CTAs (GB300: 152 SMs)
#define PROP_CTAS (152 * 6)   // co-resident grid for fused prop (occ 6 guaranteed)

// ------------------------- scratch (device globals; no allocation) ---------
__device__ __align__(256) float g_T[2][(size_t)NN * 600];   // ping-pong fp32 [N][3F]
__device__ __align__(256) __nv_bfloat16 g_AH[2][(size_t)NN * LDK_BIG];
__device__ __align__(256) __nv_bfloat16 g_AL[2][(size_t)NN * LDK_BIG];
__device__ __align__(256) __nv_bfloat16 g_B4h[4][256 * LDK_BIG];
__device__ __align__(256) __nv_bfloat16 g_B4l[4][256 * LDK_BIG];
__device__ int   g_src[EE], g_dstv[EE];
__device__ int2  g_cw[EE];                 // packed (col, weight-bits) CSR payload
__device__ int   g_deg[NN], g_indeg[NN], g_cursor[NN], g_batch[NN];
__device__ float g_dis[NN], g_diag[NN];
__device__ int   g_rowptr[NN + 1];
__device__ int   g_bsum[64];
__device__ int   g_barcnt = 0, g_barphase = 0;
__device__ int   g_is64;

__device__ __forceinline__ uint32_t smem_to_u32(const void* p) {
    uint32_t a;
    asm("{ .reg .u64 t; cvta.to.shared.u64 t, %1; cvt.u32.u64 %0, t; }" : "=r"(a) : "l"(p));
    return a;
}

// sense-reversing grid barrier (all CTAs must be co-resident)
__device__ __forceinline__ void grid_barrier(int nb) {
    __threadfence();
    __syncthreads();
    if (threadIdx.x == 0) {
        int ph = *((volatile int*)&g_barphase);
        int t = atomicAdd(&g_barcnt, 1);
        if (t == nb - 1) {
            g_barcnt = 0;
            __threadfence();
            *((volatile int*)&g_barphase) = ph ^ 1;
        } else {
            while (*((volatile int*)&g_barphase) == ph) { }
        }
    }
    __syncthreads();
}

// ------------------------- init: zero counters + dtype detect ---------------
__global__ void k_init(const void* ei) {
    int i = blockIdx.x * blockDim.x + threadIdx.x;
    if (i < NN) { g_deg[i] = 0; g_indeg[i] = 0; g_cursor[i] = 0; }
    if (i == 0) {
        const unsigned* u = (const unsigned*)ei;
        int z = 0;
        for (int j = 0; j < 32; j++)
            if (u[2 * j + 1] == 0u) z++;
        g_is64 = (z >= 16) ? 1 : 0;   // int64 little-endian: high words all zero
    }
}

// ---------- fused: edge/batch convert + degree atomics + x copy -------------
__global__ void k_cvt_all(const void* ei, const void* b, const float* __restrict__ x) {
    int stride = gridDim.x * blockDim.x;
    int t0 = blockIdx.x * blockDim.x + threadIdx.x;
    int is64 = g_is64;
    if (is64) {
        const long long* p = (const long long*)ei;
        for (int e = t0; e < EE; e += stride) {
            int s = (int)p[e], d = (int)p[EE + e];
            g_src[e] = s; g_dstv[e] = d;
            atomicAdd(&g_deg[s], 1);
            atomicAdd(&g_indeg[d], 1);
        }
        const long long* pb = (const long long*)b;
        for (int n = t0; n < NN; n += stride) g_batch[n] = (int)pb[n];
    } else {
        const int* p = (const int*)ei;
        for (int e = t0; e < EE; e += stride) {
            int s = p[e], d = p[EE + e];
            g_src[e] = s; g_dstv[e] = d;
            atomicAdd(&g_deg[s], 1);
            atomicAdd(&g_indeg[d], 1);
        }
        const int* pb = (const int*)b;
        for (int n = t0; n < NN; n += stride) g_batch[n] = pb[n];
    }
    for (int i = t0; i < NN * FIN; i += stride) {
        int n = i >> 6, f = i & 63;
        float v = x[i];
        g_T[0][(size_t)n * 192 + f] = v;
        __nv_bfloat16 h = __float2bfloat16(v);
        size_t o = (size_t)n * LDK_S + f;
        g_AH[0][o] = h;
        g_AL[0][o] = __float2bfloat16(v - __bfloat162float(h));
    }
}

// scan pass 1 + node-constants fused (dis/diag need deg, independent of scan)
__global__ void k_scan1(const float* __restrict__ lmax) {
    __shared__ int s[1024];
    int tid = threadIdx.x;
    int i = blockIdx.x * 1024 + tid;
    if (i < NN) {
        int d = g_deg[i];
        g_dis[i]  = (d > 0) ? (1.0f / sqrtf((float)d)) : 0.0f;
        g_diag[i] = 2.0f / lmax[g_batch[i]] - 1.0f;
    }
    int v = (i < NN) ? g_indeg[i] : 0;
    int xv = v;
    for (int off = 1; off < 1024; off <<= 1) {
        s[tid] = xv; __syncthreads();
        if (tid >= off) xv += s[tid - off];
        __syncthreads();
    }
    if (i < NN) g_rowptr[i] = xv - v;        // exclusive, pre-offset
    if (tid == 1023) g_bsum[blockIdx.x] = xv;
}

// scan pass 2+3 fused: each block sums its block-prefix locally, then offsets
__global__ void k_scan23(int nb) {
    __shared__ int s_red[64];
    __shared__ int s_off;
    int tid = threadIdx.x;
    if (tid < 64) s_red[tid] = (tid < blockIdx.x && tid < nb) ? g_bsum[tid] : 0;
    __syncthreads();
    if (tid == 0) {
        int acc = 0;
        for (int j = 0; j < 64; j++) acc += s_red[j];
        s_off = acc;
    }
    __syncthreads();
    int i = blockIdx.x * 1024 + tid;
    if (i < NN) g_rowptr[i] += s_off;
    if (i == 0) g_rowptr[NN] = EE;
}

// fill CSR; edge weight computed inline
__global__ void k_fill(const float* __restrict__ lmax) {
    int e = blockIdx.x * blockDim.x + threadIdx.x;
    if (e >= EE) return;
    int s = g_src[e], d = g_dstv[e];
    float w = -g_dis[s] * g_dis[d] * (2.0f / lmax[g_batch[s]]);
    int pos = g_rowptr[d] + atomicAdd(&g_cursor[d], 1);
    g_cw[pos] = make_int2(s, __float_as_int(w));
}

// zero K-pad cols [600,640) of both A buffers.
// MUST run after the layer-1 GEMM (LDK_S layout aliases these offsets before).
__global__ void k_padzero() {
    int i = blockIdx.x * blockDim.x + threadIdx.x;
    if (i >= NN * 40) return;
    size_t o = (size_t)(i / 40) * LDK_BIG + 600 + (i % 40);
    __nv_bfloat16 z = __float2bfloat16(0.0f);
    g_AH[0][o] = z; g_AL[0][o] = z;
    g_AH[1][o] = z; g_AL[1][o] = z;
}

// ------------------- fused prop pair (persistent + grid barrier) ------------
// phase1: Tx1 = L·h  (write fp32 slice1 + bf16 @aoff1)
// barrier
// phase2: Tx2 = 2·L·Tx1 − h  (write bf16 @aoff2 only)
template <int F, int LD>
__device__ __forceinline__ void prop_phase(
        float* base, int srcS, float alpha, float beta, int useSub, int writeF32,
        __nv_bfloat16* __restrict__ Ah, __nv_bfloat16* __restrict__ Al,
        int aoff, int lda, int w, int lane) {
    const float* hs  = base + srcS * F;
    float*       out = base + (srcS + 1) * F;
    const float* sub = base;
    constexpr int NQ = F / 4;
    constexpr int NJ = (NQ + 31) / 32;
    float4 acc[NJ];
#pragma unroll
    for (int j = 0; j < NJ; j++) acc[j] = make_float4(0.f, 0.f, 0.f, 0.f);

    int e = g_rowptr[w], eend = g_rowptr[w + 1];
#pragma unroll 4
    for (; e < eend; e++) {
        int2 cw = __ldg(&g_cw[e]);
        float we = __int_as_float(cw.y);
        const float4* row = (const float4*)(hs + (size_t)cw.x * LD);
#pragma unroll
        for (int j = 0; j < NJ; j++) {
            int q = lane + 32 * j;
            if (q < NQ) {
                float4 r = __ldg(&row[q]);
                acc[j].x += we * r.x;
                acc[j].y += we * r.y;
                acc[j].z += we * r.z;
                acc[j].w += we * r.w;
            }
        }
    }
    float dg = g_diag[w];
    const float4* hrow = (const float4*)(hs  + (size_t)w * LD);
    float4*       orow = (float4*)      (out + (size_t)w * LD);
    const float4* srow = (const float4*)(sub + (size_t)w * LD);
    size_t abase = (size_t)w * lda + aoff;
#pragma unroll
    for (int j = 0; j < NJ; j++) {
        int q = lane + 32 * j;
        if (q < NQ) {
            float4 h4 = hrow[q];
            float4 v;
            v.x = alpha * (acc[j].x + dg * h4.x);
            v.y = alpha * (acc[j].y + dg * h4.y);
            v.z = alpha * (acc[j].z + dg * h4.z);
            v.w = alpha * (acc[j].w + dg * h4.w);
            if (useSub) {
                float4 s4 = srow[q];
                v.x += beta * s4.x; v.y += beta * s4.y;
                v.z += beta * s4.z; v.w += beta * s4.w;
            }
            if (writeF32) orow[q] = v;
            __nv_bfloat16 h0 = __float2bfloat16(v.x);
            __nv_bfloat16 h1 = __float2bfloat16(v.y);
            __nv_bfloat16 h2 = __float2bfloat16(v.z);
            __nv_bfloat16 h3 = __float2bfloat16(v.w);
            uint2 hp, lp;
            hp.x = (uint32_t)__bfloat16_as_ushort(h0) | ((uint32_t)__bfloat16_as_ushort(h1) << 16);
            hp.y = (uint32_t)__bfloat16_as_ushort(h2) | ((uint32_t)__bfloat16_as_ushort(h3) << 16);
            __nv_bfloat16 l0 = __float2bfloat16(v.x - __bfloat162float(h0));
            __nv_bfloat16 l1 = __float2bfloat16(v.y - __bfloat162float(h1));
            __nv_bfloat16 l2 = __float2bfloat16(v.z - __bfloat162float(h2));
            __nv_bfloat16 l3 = __float2bfloat16(v.w - __bfloat162float(h3));
            lp.x = (uint32_t)__bfloat16_as_ushort(l0) | ((uint32_t)__bfloat16_as_ushort(l1) << 16);
            lp.y = (uint32_t)__bfloat16_as_ushort(l2) | ((uint32_t)__bfloat16_as_ushort(l3) << 16);
            *(uint2*)(Ah + abase + 4 * q) = hp;
            *(uint2*)(Al + abase + 4 * q) = lp;
        }
    }
}

template <int F, int LD>
__global__ __launch_bounds__(256, 6) void k_prop_fused(
        int sel, __nv_bfloat16* __restrict__ Ah, __nv_bfloat16* __restrict__ Al,
        int aoff1, int aoff2, int lda) {
    int lane = threadIdx.x & 31;
    int gwarp = blockIdx.x * 8 + (threadIdx.x >> 5);
    const int GW = PROP_CTAS * 8;
    float* base = g_T[sel];

    for (int w = gwarp; w < NN; w += GW)
        prop_phase<F, LD>(base, 0, 1.0f, 0.0f, 0, 1, Ah, Al, aoff1, lda, w, lane);

    grid_barrier(PROP_CTAS);

    for (int w = gwarp; w < NN; w += GW)
        prop_phase<F, LD>(base, 1, 2.0f, -1.0f, 1, 0, Ah, Al, aoff2, lda, w, lane);
}

// ---------------- all-layers W -> bf16 hi/lo (one launch) -------------------
__global__ void k_cvtB_all(const float* __restrict__ W1, const float* __restrict__ W2,
                           const float* __restrict__ W3, const float* __restrict__ W4) {
    int layer = blockIdx.z;
    const float* W = (layer == 0) ? W1 : (layer == 1) ? W2 : (layer == 2) ? W3 : W4;
    int LDK = layer ? LDK_BIG : LDK_S;
    int Kd  = layer ? 600 : 192;
    int k = blockIdx.x * 64 + threadIdx.x;
    int n = blockIdx.y;
    if (k >= LDK) return;
    float v = (n < HH && k < Kd) ? W[(size_t)k * HH + n] : 0.0f;
    __nv_bfloat16 h = __float2bfloat16(v);
    __nv_bfloat16 l = __float2bfloat16(v - __bfloat162float(h));
    size_t o = (size_t)n * LDK + k;
    g_B4h[layer][o] = h;
    g_B4l[layer][o] = l;
}

// ------------------------- HMMA GEMM (mma.sync bf16 3-split, fp32 acc) -----
#define SA_B   144
#define OA_H   0
#define OA_L   18432
#define OB_H   36864
#define OB_L   69120
#define STG    101376
#define SM_TOT (2 * STG)

__device__ __forceinline__ void ldsm_x4(uint32_t addr, uint32_t& r0, uint32_t& r1,
                                        uint32_t& r2, uint32_t& r3) {
    asm volatile("ldmatrix.sync.aligned.m8n8.x4.shared.b16 {%0,%1,%2,%3}, [%4];"
                 : "=r"(r0), "=r"(r1), "=r"(r2), "=r"(r3) : "r"(addr));
}
__device__ __forceinline__ void ldsm_x2(uint32_t addr, uint32_t& r0, uint32_t& r1) {
    asm volatile("ldmatrix.sync.aligned.m8n8.x2.shared.b16 {%0,%1}, [%2];"
                 : "=r"(r0), "=r"(r1) : "r"(addr));
}
__device__ __forceinline__ void mma16816(float* c, const uint32_t* a, const uint32_t* b) {
    asm volatile(
        "mma.sync.aligned.m16n8k16.row.col.f32.bf16.bf16.f32 "
        "{%0,%1,%2,%3}, {%4,%5,%6,%7}, {%8,%9}, {%0,%1,%2,%3};"
        : "+f"(c[0]), "+f"(c[1]), "+f"(c[2]), "+f"(c[3])
        : "r"(a[0]), "r"(a[1]), "r"(a[2]), "r"(a[3]), "r"(b[0]), "r"(b[1]));
}
__device__ __forceinline__ void cp16(uint32_t daddr, const void* saddr, uint32_t srcsz) {
    asm volatile("cp.async.cg.shared.global [%0], [%1], 16, %2;"
                 :: "r"(daddr), "l"(saddr), "r"(srcsz) : "memory");
}

__global__ __launch_bounds__(256, 1) void k_gemm_mma(
        const __nv_bfloat16* __restrict__ Ah, const __nv_bfloat16* __restrict__ Al,
        const __nv_bfloat16* __restrict__ Bh, const __nv_bfloat16* __restrict__ Bl,
        int LDK, int nch, const float* __restrict__ bias, int selC,
        __nv_bfloat16* __restrict__ nAh, __nv_bfloat16* __restrict__ nAl) {
    extern __shared__ char smdyn[];
    uint32_t sb = smem_to_u32(smdyn);
    int tid = threadIdx.x, lane = tid & 31, wid = tid >> 5;
    int warpM = wid >> 2, warpN = wid & 3;
    int mrow0 = warpM * 64;
    int ncol0 = warpN * 56;
    const int ldk8 = LDK >> 3;
    const int ntiles = (NN + 127) >> 7;   // 391

    const uint4* GAh = (const uint4*)Ah;
    const uint4* GAl = (const uint4*)Al;
    const uint4* GBh = (const uint4*)Bh;
    const uint4* GBl = (const uint4*)Bl;

    int rr = lane & 7;
    int aRow = rr + 8 * ((lane >> 3) & 1);
    int aK   = 8 * (lane >> 4);
    int bg   = lane >> 3;
    int bRow = rr + 8 * (bg >> 1);
    int bK   = 8 * (bg & 1);
    int bg2  = bg & 1;

    int lrow = tid >> 3, lcc = tid & 7;

    auto issue_stage = [&](int m0, int c, int s) {
        int k8 = c * 8;
        uint32_t sbase = sb + s * STG;
#pragma unroll
        for (int i = 0; i < 4; i++) {
            int row = lrow + 32 * i;
            int gm = m0 + row;
            int ok = (gm < NN);
            size_t gi = (size_t)(ok ? gm : 0) * ldk8 + k8 + lcc;
            uint32_t d = sbase + OA_H + row * SA_B + lcc * 16;
            cp16(d, GAh + gi, ok ? 16u : 0u);
            cp16(d + (OA_L - OA_H), GAl + gi, ok ? 16u : 0u);
        }
#pragma unroll
        for (int i = 0; i < 7; i++) {
            int row = lrow + 32 * i;
            size_t gi = (size_t)row * ldk8 + k8 + lcc;
            uint32_t d = sbase + OB_H + row * SA_B + lcc * 16;
            cp16(d, GBh + gi, 16u);
            cp16(d + (OB_L - OB_H), GBl + gi, 16u);
        }
        asm volatile("cp.async.commit_group;" ::: "memory");
    };

    int p = 0;
    if ((int)blockIdx.x < ntiles) issue_stage(blockIdx.x * 128, 0, 0);

    for (int t = blockIdx.x; t < ntiles; t += gridDim.x) {
        int m0 = t * 128;

        float acc[4][7][4];
#pragma unroll
        for (int i = 0; i < 4; i++)
#pragma unroll
            for (int j = 0; j < 7; j++)
#pragma unroll
                for (int q = 0; q < 4; q++) acc[i][j][q] = 0.0f;

        for (int c = 0; c < nch; c++) {
            asm volatile("cp.async.wait_group 0;" ::: "memory");
            __syncthreads();
            if (c + 1 < nch)
                issue_stage(m0, c + 1, p ^ 1);
            else if (t + (int)gridDim.x < ntiles)
                issue_stage((t + gridDim.x) * 128, 0, p ^ 1);

            uint32_t aH = sb + p * STG + OA_H;
            uint32_t aL = sb + p * STG + OA_L;
            uint32_t bH = sb + p * STG + OB_H;
            uint32_t bL = sb + p * STG + OB_L;

#pragma unroll
            for (int ks = 0; ks < 4; ks++) {
                int kel = ks * 16;
                uint32_t bh[7][2], bl[7][2];
#pragma unroll
                for (int q = 0; q < 3; q++) {
                    uint32_t boff = (uint32_t)((ncol0 + q * 16 + bRow) * SA_B + (kel + bK) * 2);
                    ldsm_x4(bH + boff, bh[2*q][0], bh[2*q][1], bh[2*q+1][0], bh[2*q+1][1]);
                    ldsm_x4(bL + boff, bl[2*q][0], bl[2*q][1], bl[2*q+1][0], bl[2*q+1][1]);
                }
                {
                    uint32_t boff = (uint32_t)((ncol0 + 48 + rr) * SA_B + (kel + 8 * bg2) * 2);
                    ldsm_x2(bH + boff, bh[6][0], bh[6][1]);
                    ldsm_x2(bL + boff, bl[6][0], bl[6][1]);
                }
#pragma unroll
                for (int mt = 0; mt < 4; mt++) {
                    uint32_t aoff = (uint32_t)((mrow0 + mt * 16 + aRow) * SA_B + (kel + aK) * 2);
                    uint32_t ah[4], al[4];
                    ldsm_x4(aH + aoff, ah[0], ah[1], ah[2], ah[3]);
                    ldsm_x4(aL + aoff, al[0], al[1], al[2], al[3]);
#pragma unroll
                    for (int nt = 0; nt < 7; nt++) {
                        mma16816(acc[mt][nt], ah, bh[nt]);
                        mma16816(acc[mt][nt], ah, bl[nt]);
                        mma16816(acc[mt][nt], al, bh[nt]);
                    }
                }
            }
            p ^= 1;
        }

        // epilogue: bias + relu; vectorized stores
        float* C = g_T[selC];
        int qrow = lane >> 2, qcol = (lane & 3) * 2;
#pragma unroll
        for (int mt = 0; mt < 4; mt++) {
            int row = m0 + mrow0 + mt * 16 + qrow;
#pragma unroll
            for (int nt = 0; nt < 7; nt++) {
                int col = ncol0 + nt * 8 + qcol;
                if (col < HH) {
                    float bz0 = __ldg(&bias[col]);
                    float bz1 = __ldg(&bias[col + 1]);
#pragma unroll
                    for (int half = 0; half < 2; half++) {
                        int r = row + 8 * half;
                        if (r < NN) {
                            float v0 = fmaxf(acc[mt][nt][2 * half]     + bz0, 0.0f);
                            float v1 = fmaxf(acc[mt][nt][2 * half + 1] + bz1, 0.0f);
                            *(float2*)(C + (size_t)r * 600 + col) = make_float2(v0, v1);
                            if (nAh) {
                                size_t ab = (size_t)r * LDK_BIG + col;
                                __nv_bfloat16 h0 = __float2bfloat16(v0);
                                __nv_bfloat16 h1 = __float2bfloat16(v1);
                                uint32_t hp = (uint32_t)__bfloat16_as_ushort(h0) |
                                              ((uint32_t)__bfloat16_as_ushort(h1) << 16);
                                __nv_bfloat16 l0 = __float2bfloat16(v0 - __bfloat162float(h0));
                                __nv_bfloat16 l1 = __float2bfloat16(v1 - __bfloat162float(h1));
                                uint32_t lp = (uint32_t)__bfloat16_as_ushort(l0) |
                                              ((uint32_t)__bfloat16_as_ushort(l1) << 16);
                                *(uint32_t*)(nAh + ab) = hp;
                                *(uint32_t*)(nAl + ab) = lp;
                            }
                        }
                    }
                }
            }
        }
    }
}

// ---------------- pooling + fc + log_softmax, fused per graph ---------------
__global__ void k_poolfc(const float* __restrict__ fw, const float* __restrict__ fb,
                         float* __restrict__ out) {
    __shared__ float4 ssum[4][52], smax[4][52];
    __shared__ float spool[400];
    int g = blockIdx.x;
    int q = threadIdx.x & 63, rg = threadIdx.x >> 6;
    // segment bounds via binary search (batch sorted ascending)
    int lo = 0, hi = NN;
    while (lo < hi) { int m = (lo + hi) >> 1; if (g_batch[m] < g) lo = m + 1; else hi = m; }
    int s = lo;
    lo = 0; hi = NN;
    while (lo < hi) { int m = (lo + hi) >> 1; if (g_batch[m] < g + 1) lo = m + 1; else hi = m; }
    int e = lo;

    float4 sum = make_float4(0.f, 0.f, 0.f, 0.f);
    float4 mx  = make_float4(-3.4e38f, -3.4e38f, -3.4e38f, -3.4e38f);
    if (q < 50) {
        for (int n = s + rg; n < e; n += 4) {
            const float4* row = (const float4*)(g_T[0] + (size_t)n * 600);
            float4 v = __ldg(&row[q]);
            sum.x += v.x; sum.y += v.y; sum.z += v.z; sum.w += v.w;
            mx.x = fmaxf(mx.x, v.x); mx.y = fmaxf(mx.y, v.y);
            mx.z = fmaxf(mx.z, v.z); mx.w = fmaxf(mx.w, v.w);
        }
        ssum[rg][q] = sum; smax[rg][q] = mx;
    }
    __syncthreads();
    if (rg == 0 && q < 50) {
#pragma unroll
        for (int r = 1; r < 4; r++) {
            float4 a = ssum[r][q], b = smax[r][q];
            sum.x += a.x; sum.y += a.y; sum.z += a.z; sum.w += a.w;
            mx.x = fmaxf(mx.x, b.x); mx.y = fmaxf(mx.y, b.y);
            mx.z = fmaxf(mx.z, b.z); mx.w = fmaxf(mx.w, b.w);
        }
        float c = fmaxf((float)(e - s), 1.0f);
        spool[4 * q]     = sum.x / c; spool[4 * q + 1] = sum.y / c;
        spool[4 * q + 2] = sum.z / c; spool[4 * q + 3] = sum.w / c;
        spool[HH + 4 * q]     = mx.x; spool[HH + 4 * q + 1] = mx.y;
        spool[HH + 4 * q + 2] = mx.z; spool[HH + 4 * q + 3] = mx.w;
    }
    __syncthreads();
    // warp 0: fc dot + log_softmax
    if (threadIdx.x < 32) {
        int lane = threadIdx.x;
        float z0 = 0.0f, z1 = 0.0f;
        for (int j = lane; j < 400; j += 32) {
            float v = spool[j];
            z0 += v * __ldg(&fw[2 * j]);
            z1 += v * __ldg(&fw[2 * j + 1]);
        }
#pragma unroll
        for (int off = 16; off > 0; off >>= 1) {
            z0 += __shfl_xor_sync(0xFFFFFFFF, z0, off);
            z1 += __shfl_xor_sync(0xFFFFFFFF, z1, off);
        }
        if (lane == 0) {
            z0 += fb[0]; z1 += fb[1];
            float m = fmaxf(z0, z1);
            float l = m + logf(expf(z0 - m) + expf(z1 - m));
            out[2 * g]     = z0 - l;
            out[2 * g + 1] = z1 - l;
        }
    }
}

// ------------------------- launch ------------------------------------------
extern "C" void kernel_launch(void* const* d_in, const int* in_sizes, int n_in,
                              void* d_out, int out_size) {
    const float* x     = (const float*)d_in[0];
    const void*  ei    = d_in[1];
    const void*  batch = d_in[2];
    const float* lmax  = (const float*)d_in[3];
    const float* W1 = (const float*)d_in[4];  const float* b1 = (const float*)d_in[5];
    const float* W2 = (const float*)d_in[6];  const float* b2 = (const float*)d_in[7];
    const float* W3 = (const float*)d_in[8];  const float* b3 = (const float*)d_in[9];
    const float* W4 = (const float*)d_in[10]; const float* b4 = (const float*)d_in[11];
    const float* fw = (const float*)d_in[12]; const float* fb = (const float*)d_in[13];
    float* out = (float*)d_out;

    cudaFuncSetAttribute(k_gemm_mma, cudaFuncAttributeMaxDynamicSharedMemorySize, SM_TOT);

    const int TB = 256;
    int nbN = (NN + TB - 1) / TB;
    int nbE = (EE + TB - 1) / TB;
    int nbS = (NN + 1023) / 1024;

    __nv_bfloat16 *AH0, *AL0, *AH1, *AL1, *BH, *BL;
    cudaGetSymbolAddress((void**)&AH0, g_AH);  AH1 = AH0 + (size_t)NN * LDK_BIG;
    cudaGetSymbolAddress((void**)&AL0, g_AL);  AL1 = AL0 + (size_t)NN * LDK_BIG;
    cudaGetSymbolAddress((void**)&BH, g_B4h);
    cudaGetSymbolAddress((void**)&BL, g_B4l);
    const size_t BSTR = (size_t)256 * LDK_BIG;

    // independent weight conversion first (off the critical chain)
    k_cvtB_all<<<dim3(10, 256, 4), 64>>>(W1, W2, W3, W4);

    k_init<<<nbN, TB>>>(ei);
    k_cvt_all<<<nbE, TB>>>(ei, batch, x);
    k_scan1<<<nbS, 1024>>>(lmax);
    k_scan23<<<nbS, 1024>>>(nbS);
    k_fill<<<nbE, TB>>>(lmax);

    // layer 1 (A buffers in LDK_S layout until consumed by GEMM below)
    k_prop_fused<64, 192><<<PROP_CTAS, TB>>>(0, AH0, AL0, 64, 128, LDK_S);
    k_gemm_mma<<<GEMM_GRID, 256, SM_TOT>>>(AH0, AL0, BH, BL, LDK_S, 3, b1, 1, AH1, AL1);
    k_padzero<<<(NN * 40 + TB - 1) / TB, TB>>>();   // AFTER layer-1 GEMM (layout switch)

    // layer 2
    k_prop_fused<200, 600><<<PROP_CTAS, TB>>>(1, AH1, AL1, 200, 400, LDK_BIG);
    k_gemm_mma<<<GEMM_GRID, 256, SM_TOT>>>(AH1, AL1, BH + BSTR, BL + BSTR,
                                           LDK_BIG, 10, b2, 0, AH0, AL0);
    // layer 3
    k_prop_fused<200, 600><<<PROP_CTAS, TB>>>(0, AH0, AL0, 200, 400, LDK_BIG);
    k_gemm_mma<<<GEMM_GRID, 256, SM_TOT>>>(AH0, AL0, BH + 2 * BSTR, BL + 2 * BSTR,
                                           LDK_BIG, 10, b3, 1, AH1, AL1);
    // layer 4
    k_prop_fused<200, 600><<<PROP_CTAS, TB>>>(1, AH1, AL1, 200, 400, LDK_BIG);
    k_gemm_mma<<<GEMM_GRID, 256, SM_TOT>>>(AH1, AL1, BH + 3 * BSTR, BL + 3 * BSTR,
                                           LDK_BIG, 10, b4, 0, nullptr, nullptr);

    // pooling + fc + log_softmax (fused, one launch)
    k_poolfc<<<GG, TB>>>(fw, fb, out);
}